// round 1
// baseline (speedup 1.0000x reference)
#include <cuda_runtime.h>
#include <cuda_bf16.h>

// Problem constants
#define PN 4096
#define PTOPK 2
#define PE 8
#define PH 2048
#define PI 1408
#define PNK (PN * PTOPK)   // 8192

// ---------------- device scratch (no runtime allocation allowed) ----------------
__device__ int g_counts[PE];
__device__ int g_offsets[PE + 1];
__device__ int g_cursor[PE];
__device__ int g_pair_token[PNK];
__device__ float g_pair_w[PNK];
__device__ float g_hidden[(size_t)PNK * PI];   // 46 MB scratch: silu(g)*u per (token,expert) slot

// ---------------- routing kernels ----------------
__global__ void k_zero_out(float* out, int n) {
    int i = blockIdx.x * blockDim.x + threadIdx.x;
    int stride = gridDim.x * blockDim.x;
    for (; i < n; i += stride) out[i] = 0.0f;
    if (blockIdx.x == 0 && threadIdx.x < PE) {
        g_counts[threadIdx.x] = 0;
        g_cursor[threadIdx.x] = 0;
    }
}

__global__ void k_count(const int* __restrict__ ids) {
    int i = blockIdx.x * blockDim.x + threadIdx.x;
    if (i < PNK) atomicAdd(&g_counts[ids[i]], 1);
}

__global__ void k_scan() {
    // single thread: E=8, trivial
    int s = 0;
    for (int e = 0; e < PE; e++) { g_offsets[e] = s; s += g_counts[e]; }
    g_offsets[PE] = s;
}

__global__ void k_scatter(const int* __restrict__ ids, const float* __restrict__ w) {
    int i = blockIdx.x * blockDim.x + threadIdx.x;
    if (i < PNK) {
        int e = ids[i];
        int pos = g_offsets[e] + atomicAdd(&g_cursor[e], 1);
        g_pair_token[pos] = i / PTOPK;
        g_pair_w[pos] = w[i];
    }
}

// ---------------- gate/up GEMM + SwiGLU ----------------
// C tile: 128 rows (token-slots within one expert) x 64 cols (intermediate dim),
// computes gate and up simultaneously, writes silu(g)*u to g_hidden.
#define GU_BM 128
#define GU_BN 64
#define GU_BK 16

__global__ __launch_bounds__(256) void k_gu(const float* __restrict__ x,
                                            const float* __restrict__ Wg,
                                            const float* __restrict__ Wu) {
    const int e = blockIdx.z;
    const int beg = g_offsets[e];
    const int end = g_offsets[e + 1];
    const int row0 = beg + blockIdx.y * GU_BM;
    if (row0 >= end) return;
    const int n0 = blockIdx.x * GU_BN;

    __shared__ float As[GU_BK][GU_BM + 4];
    __shared__ float Bgs[GU_BK][GU_BN + 4];
    __shared__ float Bus[GU_BK][GU_BN + 4];
    __shared__ int s_tok[GU_BM];

    const int tid = threadIdx.x;
    if (tid < GU_BM) {
        int slot = row0 + tid;
        if (slot > PNK - 1) slot = PNK - 1;
        s_tok[tid] = g_pair_token[slot];
    }
    __syncthreads();

    const float* wg_base = Wg + (size_t)e * PI * PH;
    const float* wu_base = Wu + (size_t)e * PI * PH;

    float accg[8][4];
    float accu[8][4];
#pragma unroll
    for (int i = 0; i < 8; i++)
#pragma unroll
        for (int j = 0; j < 4; j++) { accg[i][j] = 0.0f; accu[i][j] = 0.0f; }

    const int tx = tid & 15;   // col group: cols tx*4 .. tx*4+3
    const int ty = tid >> 4;   // row group: rows ty*8 .. ty*8+7

    for (int k0 = 0; k0 < PH; k0 += GU_BK) {
        // A tile: 128 rows x 16 k, 512 float4 total -> 2 per thread
#pragma unroll
        for (int it = 0; it < 2; it++) {
            int idx = tid + it * 256;
            int r = idx >> 2;
            int kq = idx & 3;
            const float4 v = *(const float4*)(x + (size_t)s_tok[r] * PH + k0 + kq * 4);
            As[kq * 4 + 0][r] = v.x;
            As[kq * 4 + 1][r] = v.y;
            As[kq * 4 + 2][r] = v.z;
            As[kq * 4 + 3][r] = v.w;
        }
        // B tiles: 64 rows(n) x 16 k, 256 float4 -> 1 per thread, for Wg and Wu
        {
            int nidx = tid >> 2;
            int kq = tid & 3;
            size_t off = (size_t)(n0 + nidx) * PH + k0 + kq * 4;
            const float4 vg = *(const float4*)(wg_base + off);
            Bgs[kq * 4 + 0][nidx] = vg.x;
            Bgs[kq * 4 + 1][nidx] = vg.y;
            Bgs[kq * 4 + 2][nidx] = vg.z;
            Bgs[kq * 4 + 3][nidx] = vg.w;
            const float4 vu = *(const float4*)(wu_base + off);
            Bus[kq * 4 + 0][nidx] = vu.x;
            Bus[kq * 4 + 1][nidx] = vu.y;
            Bus[kq * 4 + 2][nidx] = vu.z;
            Bus[kq * 4 + 3][nidx] = vu.w;
        }
        __syncthreads();

#pragma unroll
        for (int k = 0; k < GU_BK; k++) {
            float a[8], bg[4], bu[4];
            *(float4*)&a[0] = *(const float4*)&As[k][ty * 8];
            *(float4*)&a[4] = *(const float4*)&As[k][ty * 8 + 4];
            *(float4*)&bg[0] = *(const float4*)&Bgs[k][tx * 4];
            *(float4*)&bu[0] = *(const float4*)&Bus[k][tx * 4];
#pragma unroll
            for (int i = 0; i < 8; i++)
#pragma unroll
                for (int j = 0; j < 4; j++) {
                    accg[i][j] += a[i] * bg[j];
                    accu[i][j] += a[i] * bu[j];
                }
        }
        __syncthreads();
    }

    // epilogue: hidden = silu(g) * u
#pragma unroll
    for (int i = 0; i < 8; i++) {
        int slot = row0 + ty * 8 + i;
        if (slot < end) {
            float4 hv;
            float g, u;
            g = accg[i][0]; u = accu[i][0]; hv.x = (g / (1.0f + __expf(-g))) * u;
            g = accg[i][1]; u = accu[i][1]; hv.y = (g / (1.0f + __expf(-g))) * u;
            g = accg[i][2]; u = accu[i][2]; hv.z = (g / (1.0f + __expf(-g))) * u;
            g = accg[i][3]; u = accu[i][3]; hv.w = (g / (1.0f + __expf(-g))) * u;
            *(float4*)(g_hidden + (size_t)slot * PI + n0 + tx * 4) = hv;
        }
    }
}

// ---------------- down GEMM + weighted combine ----------------
#define D_BM 128
#define D_BN 128
#define D_BK 16

__global__ __launch_bounds__(256) void k_down(const float* __restrict__ Wd,
                                              float* __restrict__ out) {
    const int e = blockIdx.z;
    const int beg = g_offsets[e];
    const int end = g_offsets[e + 1];
    const int row0 = beg + blockIdx.y * D_BM;
    if (row0 >= end) return;
    const int n0 = blockIdx.x * D_BN;

    __shared__ float As[D_BK][D_BM + 4];
    __shared__ float Bs[D_BK][D_BN + 4];
    __shared__ int s_tok[D_BM];
    __shared__ float s_w[D_BM];

    const int tid = threadIdx.x;
    if (tid < D_BM) {
        int slot = row0 + tid;
        if (slot > PNK - 1) slot = PNK - 1;
        s_tok[tid] = g_pair_token[slot];
        s_w[tid] = g_pair_w[slot];
    }
    __syncthreads();

    const float* wd_base = Wd + (size_t)e * PH * PI;

    float acc[8][8];
#pragma unroll
    for (int i = 0; i < 8; i++)
#pragma unroll
        for (int j = 0; j < 8; j++) acc[i][j] = 0.0f;

    const int tx = tid & 15;   // cols tx*8 .. tx*8+7
    const int ty = tid >> 4;   // rows ty*8 .. ty*8+7

    for (int k0 = 0; k0 < PI; k0 += D_BK) {
        // A tile: 128 rows x 16 k from g_hidden
#pragma unroll
        for (int it = 0; it < 2; it++) {
            int idx = tid + it * 256;
            int r = idx >> 2;
            int kq = idx & 3;
            int slot = row0 + r;
            if (slot > PNK - 1) slot = PNK - 1;
            const float4 v = *(const float4*)(g_hidden + (size_t)slot * PI + k0 + kq * 4);
            As[kq * 4 + 0][r] = v.x;
            As[kq * 4 + 1][r] = v.y;
            As[kq * 4 + 2][r] = v.z;
            As[kq * 4 + 3][r] = v.w;
        }
        // B tile: 128 rows(n = output col over H) x 16 k from Wd[e][n][k]
#pragma unroll
        for (int it = 0; it < 2; it++) {
            int idx = tid + it * 256;
            int r = idx >> 2;
            int kq = idx & 3;
            const float4 v = *(const float4*)(wd_base + (size_t)(n0 + r) * PI + k0 + kq * 4);
            Bs[kq * 4 + 0][r] = v.x;
            Bs[kq * 4 + 1][r] = v.y;
            Bs[kq * 4 + 2][r] = v.z;
            Bs[kq * 4 + 3][r] = v.w;
        }
        __syncthreads();

#pragma unroll
        for (int k = 0; k < D_BK; k++) {
            float a[8], b[8];
            *(float4*)&a[0] = *(const float4*)&As[k][ty * 8];
            *(float4*)&a[4] = *(const float4*)&As[k][ty * 8 + 4];
            *(float4*)&b[0] = *(const float4*)&Bs[k][tx * 8];
            *(float4*)&b[4] = *(const float4*)&Bs[k][tx * 8 + 4];
#pragma unroll
            for (int i = 0; i < 8; i++)
#pragma unroll
                for (int j = 0; j < 8; j++) acc[i][j] += a[i] * b[j];
        }
        __syncthreads();
    }

    // epilogue: out[token][n] += w * acc   (K=2 contributions per token row)
#pragma unroll
    for (int i = 0; i < 8; i++) {
        int lr = ty * 8 + i;
        int slot = row0 + lr;
        if (slot < end) {
            const int tok = s_tok[lr];
            const float w = s_w[lr];
            float* op = out + (size_t)tok * PH + n0 + tx * 8;
#pragma unroll
            for (int j = 0; j < 8; j++) atomicAdd(op + j, w * acc[i][j]);
        }
    }
}

// ---------------- launch ----------------
extern "C" void kernel_launch(void* const* d_in, const int* in_sizes, int n_in,
                              void* d_out, int out_size) {
    const float* x = (const float*)d_in[0];          // [N, H]
    const int* topk_ids = (const int*)d_in[1];       // [N, K]
    const float* topk_w = (const float*)d_in[2];     // [N, K]
    const float* Wg = (const float*)d_in[3];         // [E, I, H]
    const float* Wu = (const float*)d_in[4];         // [E, I, H]
    const float* Wd = (const float*)d_in[5];         // [E, H, I]
    float* out = (float*)d_out;                      // [N, H]

    // 1) zero output + routing state
    k_zero_out<<<1024, 256>>>(out, PN * PH);
    // 2) histogram of expert assignments
    k_count<<<(PNK + 255) / 256, 256>>>(topk_ids);
    // 3) exclusive prefix sum over E=8 experts
    k_scan<<<1, 1>>>();
    // 4) scatter (token, weight) pairs into expert-grouped slots
    k_scatter<<<(PNK + 255) / 256, 256>>>(topk_ids, topk_w);
    // 5) gate/up GEMM + SwiGLU -> g_hidden
    {
        dim3 grid(PI / GU_BN, (PN + GU_BM - 1) / GU_BM, PE);
        k_gu<<<grid, 256>>>(x, Wg, Wu);
    }
    // 6) down GEMM + weighted scatter-add into out
    {
        dim3 grid(PH / D_BN, (PN + D_BM - 1) / D_BM, PE);
        k_down<<<grid, 256>>>(Wd, out);
    }
}

// round 7
// speedup vs baseline: 2.0361x; 2.0361x over previous
#include <cuda_runtime.h>
#include <cuda_bf16.h>
#include <cstdint>

// Problem constants
#define PN 4096
#define PTOPK 2
#define PE 8
#define PH 2048
#define PI 1408
#define PNK (PN * PTOPK)   // 8192

// ---------------- device scratch ----------------
__device__ int g_counts[PE];
__device__ int g_offsets[PE + 1];
__device__ int g_cursor[PE];
__device__ int g_pair_token[PNK];
__device__ float g_pair_w[PNK];

__device__ __align__(16) __nv_bfloat16 g_xhi[(size_t)PN * PH];
__device__ __align__(16) __nv_bfloat16 g_xlo[(size_t)PN * PH];
__device__ __align__(16) __nv_bfloat16 g_wghi[(size_t)PE * PI * PH];
__device__ __align__(16) __nv_bfloat16 g_wglo[(size_t)PE * PI * PH];
__device__ __align__(16) __nv_bfloat16 g_wuhi[(size_t)PE * PI * PH];
__device__ __align__(16) __nv_bfloat16 g_wulo[(size_t)PE * PI * PH];
__device__ __align__(16) __nv_bfloat16 g_wdhi[(size_t)PE * PH * PI];
__device__ __align__(16) __nv_bfloat16 g_wdlo[(size_t)PE * PH * PI];
__device__ __align__(16) __nv_bfloat16 g_hhi[(size_t)PNK * PI];
__device__ __align__(16) __nv_bfloat16 g_hlo[(size_t)PNK * PI];

// ---------------- helpers ----------------
__device__ __forceinline__ uint32_t smem_u32(const void* p) {
    return (uint32_t)__cvta_generic_to_shared(p);
}

__device__ __forceinline__ void ldsm_x4(uint32_t* r, uint32_t addr) {
    asm volatile("ldmatrix.sync.aligned.m8n8.x4.shared.b16 {%0,%1,%2,%3}, [%4];"
                 : "=r"(r[0]), "=r"(r[1]), "=r"(r[2]), "=r"(r[3]) : "r"(addr) : "memory");
}
__device__ __forceinline__ void ldsm_x2(uint32_t* r, uint32_t addr) {
    asm volatile("ldmatrix.sync.aligned.m8n8.x2.shared.b16 {%0,%1}, [%2];"
                 : "=r"(r[0]), "=r"(r[1]) : "r"(addr) : "memory");
}
__device__ __forceinline__ void mma16816(float* c, const uint32_t* a, const uint32_t* b) {
    asm volatile("mma.sync.aligned.m16n8k16.row.col.f32.bf16.bf16.f32 "
                 "{%0,%1,%2,%3}, {%4,%5,%6,%7}, {%8,%9}, {%0,%1,%2,%3};"
                 : "+f"(c[0]), "+f"(c[1]), "+f"(c[2]), "+f"(c[3])
                 : "r"(a[0]), "r"(a[1]), "r"(a[2]), "r"(a[3]), "r"(b[0]), "r"(b[1])
                 : "memory");
}

__device__ __forceinline__ float silu_f(float g) {
    return g / (1.0f + __expf(-g));
}

// ---------------- routing kernels ----------------
__global__ void k_zero_out(float* out, int n) {
    int i = blockIdx.x * blockDim.x + threadIdx.x;
    int stride = gridDim.x * blockDim.x;
    for (; i < n; i += stride) out[i] = 0.0f;
    if (blockIdx.x == 0 && threadIdx.x < PE) {
        g_counts[threadIdx.x] = 0;
        g_cursor[threadIdx.x] = 0;
    }
}

__global__ void k_count(const int* __restrict__ ids) {
    int i = blockIdx.x * blockDim.x + threadIdx.x;
    if (i < PNK) atomicAdd(&g_counts[ids[i]], 1);
}

__global__ void k_scan() {
    int s = 0;
    for (int e = 0; e < PE; e++) { g_offsets[e] = s; s += g_counts[e]; }
    g_offsets[PE] = s;
}

__global__ void k_scatter(const int* __restrict__ ids, const float* __restrict__ w) {
    int i = blockIdx.x * blockDim.x + threadIdx.x;
    if (i < PNK) {
        int e = ids[i];
        int pos = g_offsets[e] + atomicAdd(&g_cursor[e], 1);
        g_pair_token[pos] = i / PTOPK;
        g_pair_w[pos] = w[i];
    }
}

// ---------------- fp32 -> bf16 hi/lo split ----------------
// IMPORTANT: destination globals are referenced from DEVICE code only.
// Passing __device__ symbols as host-side kernel args silently resolves to
// the host shadow address (and on GB300 ATS makes writes land in host RAM).
__device__ __forceinline__ void split_body(const float* __restrict__ src,
                                           __nv_bfloat16* __restrict__ hi,
                                           __nv_bfloat16* __restrict__ lo, int n4) {
    int i = blockIdx.x * blockDim.x + threadIdx.x;
    int stride = gridDim.x * blockDim.x;
    for (; i < n4; i += stride) {
        float4 v = reinterpret_cast<const float4*>(src)[i];
        __nv_bfloat162 h0, h1, l0, l1;
        h0.x = __float2bfloat16(v.x); l0.x = __float2bfloat16(v.x - __bfloat162float(h0.x));
        h0.y = __float2bfloat16(v.y); l0.y = __float2bfloat16(v.y - __bfloat162float(h0.y));
        h1.x = __float2bfloat16(v.z); l1.x = __float2bfloat16(v.z - __bfloat162float(h1.x));
        h1.y = __float2bfloat16(v.w); l1.y = __float2bfloat16(v.w - __bfloat162float(h1.y));
        reinterpret_cast<__nv_bfloat162*>(hi)[i * 2 + 0] = h0;
        reinterpret_cast<__nv_bfloat162*>(hi)[i * 2 + 1] = h1;
        reinterpret_cast<__nv_bfloat162*>(lo)[i * 2 + 0] = l0;
        reinterpret_cast<__nv_bfloat162*>(lo)[i * 2 + 1] = l1;
    }
}

__global__ void k_split_x(const float* __restrict__ src) {
    split_body(src, g_xhi, g_xlo, PN * PH / 4);
}
__global__ void k_split_wg(const float* __restrict__ src) {
    split_body(src, g_wghi, g_wglo, PE * PI * PH / 4);
}
__global__ void k_split_wu(const float* __restrict__ src) {
    split_body(src, g_wuhi, g_wulo, PE * PI * PH / 4);
}
__global__ void k_split_wd(const float* __restrict__ src) {
    split_body(src, g_wdhi, g_wdlo, PE * PH * PI / 4);
}

// ============================================================================
// GU kernel: split-bf16 mma.sync, 128 slots x (64 gate + 64 up), BK=32.
// Static SMEM, single stage, synchronous loads.
//   A_hi 128x80B @0, A_lo @10240, Bg_hi/Bg_lo/Bu_hi/Bu_lo 64x80B @20480+t*5120
//   s_tok (128 int) @40960.  Total 41472.
// ============================================================================
__global__ __launch_bounds__(256, 2) void k_gu() {
    __shared__ __align__(128) char smem[41472];
    const int e = blockIdx.z;
    const int beg = g_offsets[e];
    const int end = g_offsets[e + 1];
    const int row0 = beg + blockIdx.x * 128;
    if (row0 >= end) return;
    const int n0 = blockIdx.y * 64;

    const int tid = threadIdx.x;
    const int wid = tid >> 5;
    const int lane = tid & 31;
    const int wr = wid >> 1;   // rows wr*32..+31
    const int wc = wid & 1;    // cols wc*32..+31

    int* s_tok = reinterpret_cast<int*>(smem + 40960);
    if (tid < 128) {
        int slot = row0 + tid;
        if (slot >= PNK) slot = PNK - 1;
        s_tok[tid] = g_pair_token[slot];
    }
    __syncthreads();

    const size_t eoff = (size_t)e * PI * PH;

    float accg[2][4][4];
    float accu[2][4][4];
#pragma unroll
    for (int mi = 0; mi < 2; mi++)
#pragma unroll
        for (int ni = 0; ni < 4; ni++)
#pragma unroll
            for (int q = 0; q < 4; q++) { accg[mi][ni][q] = 0.0f; accu[mi][ni][q] = 0.0f; }

    const uint32_t sb = smem_u32(smem);
    const uint32_t aHiB = sb + (wr * 32 + (lane & 15)) * 80 + (lane >> 4) * 16;
    const uint32_t aLoB = aHiB + 10240;
    const uint32_t bRow = (lane & 7) * 80 + ((lane >> 3) & 1) * 16;
    const uint32_t bgHiB = sb + 20480 + (wc * 32) * 80 + bRow;
    const uint32_t bgLoB = bgHiB + 5120;
    const uint32_t buHiB = bgHiB + 10240;
    const uint32_t buLoB = bgHiB + 15360;

    for (int k0 = 0; k0 < PH; k0 += 32) {
        // ---- load A: x hi/lo, 128 rows x 32 k (1024 x 16B) ----
#pragma unroll
        for (int it = 0; it < 4; it++) {
            int idx = tid + it * 256;
            int t = idx >> 9;
            int r = (idx >> 2) & 127;
            int c = idx & 3;
            const __nv_bfloat16* src =
                (t ? g_xlo : g_xhi) + (size_t)s_tok[r] * PH + k0 + c * 8;
            *reinterpret_cast<uint4*>(smem + t * 10240 + r * 80 + c * 16) =
                *reinterpret_cast<const uint4*>(src);
        }
        // ---- load B: 4 tensors x 64 rows x 32 k (1024 x 16B) ----
#pragma unroll
        for (int it = 0; it < 4; it++) {
            int idx = tid + it * 256;
            int t = idx >> 8;          // 0..3
            int r = (idx >> 2) & 63;
            int c = idx & 3;
            const __nv_bfloat16* base;
            if (t == 0) base = g_wghi;
            else if (t == 1) base = g_wglo;
            else if (t == 2) base = g_wuhi;
            else base = g_wulo;
            const __nv_bfloat16* src = base + eoff + (size_t)(n0 + r) * PH + k0 + c * 8;
            *reinterpret_cast<uint4*>(smem + 20480 + t * 5120 + r * 80 + c * 16) =
                *reinterpret_cast<const uint4*>(src);
        }
        __syncthreads();

#pragma unroll
        for (int ks = 0; ks < 2; ks++) {
            uint32_t ko = ks * 32;
            uint32_t ahi[2][4], alo[2][4];
            ldsm_x4(ahi[0], aHiB + ko);
            ldsm_x4(ahi[1], aHiB + 16 * 80 + ko);
            ldsm_x4(alo[0], aLoB + ko);
            ldsm_x4(alo[1], aLoB + 16 * 80 + ko);
#pragma unroll
            for (int ni = 0; ni < 4; ni++) {
                uint32_t bh[2], bl[2];
                ldsm_x2(bh, bgHiB + ni * 8 * 80 + ko);
                ldsm_x2(bl, bgLoB + ni * 8 * 80 + ko);
#pragma unroll
                for (int mi = 0; mi < 2; mi++) {
                    mma16816(accg[mi][ni], ahi[mi], bh);
                    mma16816(accg[mi][ni], ahi[mi], bl);
                    mma16816(accg[mi][ni], alo[mi], bh);
                }
                ldsm_x2(bh, buHiB + ni * 8 * 80 + ko);
                ldsm_x2(bl, buLoB + ni * 8 * 80 + ko);
#pragma unroll
                for (int mi = 0; mi < 2; mi++) {
                    mma16816(accu[mi][ni], ahi[mi], bh);
                    mma16816(accu[mi][ni], ahi[mi], bl);
                    mma16816(accu[mi][ni], alo[mi], bh);
                }
            }
        }
        __syncthreads();
    }

    // epilogue: h = silu(g)*u, split to bf16 hi/lo
    const int gRow = lane >> 2;
    const int cp2 = (lane & 3) * 2;
#pragma unroll
    for (int mi = 0; mi < 2; mi++) {
#pragma unroll
        for (int ni = 0; ni < 4; ni++) {
            int col = n0 + wc * 32 + ni * 8 + cp2;
            int r0 = wr * 32 + mi * 16 + gRow;
#pragma unroll
            for (int half = 0; half < 2; half++) {
                int slot = row0 + r0 + half * 8;
                if (slot < end) {
                    float g0 = accg[mi][ni][half * 2 + 0];
                    float g1 = accg[mi][ni][half * 2 + 1];
                    float u0 = accu[mi][ni][half * 2 + 0];
                    float u1 = accu[mi][ni][half * 2 + 1];
                    float h0 = silu_f(g0) * u0;
                    float h1 = silu_f(g1) * u1;
                    __nv_bfloat162 vh, vl;
                    vh.x = __float2bfloat16(h0);
                    vl.x = __float2bfloat16(h0 - __bfloat162float(vh.x));
                    vh.y = __float2bfloat16(h1);
                    vl.y = __float2bfloat16(h1 - __bfloat162float(vh.y));
                    *reinterpret_cast<__nv_bfloat162*>(g_hhi + (size_t)slot * PI + col) = vh;
                    *reinterpret_cast<__nv_bfloat162*>(g_hlo + (size_t)slot * PI + col) = vl;
                }
            }
        }
    }
}

// ============================================================================
// Down kernel: 128 slots x 128 H-cols, BK=32 over I. Static SMEM single stage.
//   A_hi @0, A_lo @10240, B_hi @20480, B_lo @30720, s_tok @40960, s_w @41472.
//   Total 41984. Epilogue: atomicAdd(out, w * acc).
// ============================================================================
__global__ __launch_bounds__(256, 2) void k_down(float* __restrict__ out) {
    __shared__ __align__(128) char smem[41984];
    const int e = blockIdx.z;
    const int beg = g_offsets[e];
    const int end = g_offsets[e + 1];
    const int row0 = beg + blockIdx.x * 128;
    if (row0 >= end) return;
    const int n0 = blockIdx.y * 128;

    const int tid = threadIdx.x;
    const int wid = tid >> 5;
    const int lane = tid & 31;
    const int wr = wid >> 1;   // rows wr*32..+31
    const int wc = wid & 1;    // cols wc*64..+63

    int* s_tok = reinterpret_cast<int*>(smem + 40960);
    float* s_w = reinterpret_cast<float*>(smem + 41472);
    if (tid < 128) {
        int slot = row0 + tid;
        if (slot >= PNK) slot = PNK - 1;
        s_tok[tid] = g_pair_token[slot];
        s_w[tid] = g_pair_w[slot];
    }
    __syncthreads();

    const size_t eoff = (size_t)e * PH * PI;

    float acc[2][8][4];
#pragma unroll
    for (int mi = 0; mi < 2; mi++)
#pragma unroll
        for (int ni = 0; ni < 8; ni++)
#pragma unroll
            for (int q = 0; q < 4; q++) acc[mi][ni][q] = 0.0f;

    const uint32_t sb = smem_u32(smem);
    const uint32_t aHiB = sb + (wr * 32 + (lane & 15)) * 80 + (lane >> 4) * 16;
    const uint32_t aLoB = aHiB + 10240;
    const uint32_t bRow = (lane & 7) * 80 + ((lane >> 3) & 1) * 16;
    const uint32_t bHiB = sb + 20480 + (wc * 64) * 80 + bRow;
    const uint32_t bLoB = bHiB + 10240;

    for (int k0 = 0; k0 < PI; k0 += 32) {
        // ---- load A: hidden hi/lo, 128 rows x 32 k ----
#pragma unroll
        for (int it = 0; it < 4; it++) {
            int idx = tid + it * 256;
            int t = idx >> 9;
            int r = (idx >> 2) & 127;
            int c = idx & 3;
            int slot = row0 + r;
            if (slot >= PNK) slot = PNK - 1;
            const __nv_bfloat16* src =
                (t ? g_hlo : g_hhi) + (size_t)slot * PI + k0 + c * 8;
            *reinterpret_cast<uint4*>(smem + t * 10240 + r * 80 + c * 16) =
                *reinterpret_cast<const uint4*>(src);
        }
        // ---- load B: wd hi/lo, 128 rows x 32 k ----
#pragma unroll
        for (int it = 0; it < 4; it++) {
            int idx = tid + it * 256;
            int t = idx >> 9;
            int r = (idx >> 2) & 127;
            int c = idx & 3;
            const __nv_bfloat16* src =
                (t ? g_wdlo : g_wdhi) + eoff + (size_t)(n0 + r) * PI + k0 + c * 8;
            *reinterpret_cast<uint4*>(smem + 20480 + t * 10240 + r * 80 + c * 16) =
                *reinterpret_cast<const uint4*>(src);
        }
        __syncthreads();

#pragma unroll
        for (int ks = 0; ks < 2; ks++) {
            uint32_t ko = ks * 32;
            uint32_t ahi[2][4], alo[2][4];
            ldsm_x4(ahi[0], aHiB + ko);
            ldsm_x4(ahi[1], aHiB + 16 * 80 + ko);
            ldsm_x4(alo[0], aLoB + ko);
            ldsm_x4(alo[1], aLoB + 16 * 80 + ko);
#pragma unroll
            for (int ni = 0; ni < 8; ni++) {
                uint32_t bh[2], bl[2];
                ldsm_x2(bh, bHiB + ni * 8 * 80 + ko);
                ldsm_x2(bl, bLoB + ni * 8 * 80 + ko);
#pragma unroll
                for (int mi = 0; mi < 2; mi++) {
                    mma16816(acc[mi][ni], ahi[mi], bh);
                    mma16816(acc[mi][ni], ahi[mi], bl);
                    mma16816(acc[mi][ni], alo[mi], bh);
                }
            }
        }
        __syncthreads();
    }

    // epilogue: out[token][col] += w * acc
    const int gRow = lane >> 2;
    const int cp2 = (lane & 3) * 2;
#pragma unroll
    for (int mi = 0; mi < 2; mi++) {
#pragma unroll
        for (int ni = 0; ni < 8; ni++) {
            int col = n0 + wc * 64 + ni * 8 + cp2;
            int r0 = wr * 32 + mi * 16 + gRow;
#pragma unroll
            for (int half = 0; half < 2; half++) {
                int lr = r0 + half * 8;
                int slot = row0 + lr;
                if (slot < end) {
                    const int tok = s_tok[lr];
                    const float w = s_w[lr];
                    float* op = out + (size_t)tok * PH + col;
                    atomicAdd(op + 0, w * acc[mi][ni][half * 2 + 0]);
                    atomicAdd(op + 1, w * acc[mi][ni][half * 2 + 1]);
                }
            }
        }
    }
}

// ---------------- launch ----------------
extern "C" void kernel_launch(void* const* d_in, const int* in_sizes, int n_in,
                              void* d_out, int out_size) {
    const float* x = (const float*)d_in[0];          // [N, H]
    const int* topk_ids = (const int*)d_in[1];       // [N, K]
    const float* topk_w = (const float*)d_in[2];     // [N, K]
    const float* Wg = (const float*)d_in[3];         // [E, I, H]
    const float* Wu = (const float*)d_in[4];         // [E, I, H]
    const float* Wd = (const float*)d_in[5];         // [E, H, I]
    float* out = (float*)d_out;                      // [N, H]

    // routing + zero output
    k_zero_out<<<1024, 256>>>(out, PN * PH);
    k_count<<<(PNK + 255) / 256, 256>>>(topk_ids);
    k_scan<<<1, 1>>>();
    k_scatter<<<(PNK + 255) / 256, 256>>>(topk_ids, topk_w);

    // fp32 -> bf16 hi/lo splits (destinations resolved in device code)
    k_split_x<<<4096, 256>>>(x);
    k_split_wg<<<8192, 256>>>(Wg);
    k_split_wu<<<8192, 256>>>(Wu);
    k_split_wd<<<8192, 256>>>(Wd);

    // gate/up GEMM + SwiGLU -> hidden hi/lo
    {
        dim3 grid(PN / 128, PI / 64, PE);    // 32 x 22 x 8
        k_gu<<<grid, 256>>>();
    }
    // down GEMM -> weighted atomic combine into out
    {
        dim3 grid(PN / 128, PH / 128, PE);   // 32 x 16 x 8
        k_down<<<grid, 256>>>(out);
    }
}

// round 8
// speedup vs baseline: 2.2810x; 1.1203x over previous
#include <cuda_runtime.h>
#include <cuda_bf16.h>
#include <cstdint>

// Problem constants
#define PN 4096
#define PTOPK 2
#define PE 8
#define PH 2048
#define PI 1408
#define PNK (PN * PTOPK)   // 8192

// ---------------- device scratch ----------------
__device__ int g_counts[PE];
__device__ int g_offsets[PE + 1];
__device__ int g_cursor[PE];
__device__ int g_pair_token[PNK];
__device__ float g_pair_w[PNK];

__device__ __align__(16) __nv_bfloat16 g_xhi[(size_t)PN * PH];
__device__ __align__(16) __nv_bfloat16 g_xlo[(size_t)PN * PH];
__device__ __align__(16) __nv_bfloat16 g_wghi[(size_t)PE * PI * PH];
__device__ __align__(16) __nv_bfloat16 g_wglo[(size_t)PE * PI * PH];
__device__ __align__(16) __nv_bfloat16 g_wuhi[(size_t)PE * PI * PH];
__device__ __align__(16) __nv_bfloat16 g_wulo[(size_t)PE * PI * PH];
__device__ __align__(16) __nv_bfloat16 g_wdhi[(size_t)PE * PH * PI];
__device__ __align__(16) __nv_bfloat16 g_wdlo[(size_t)PE * PH * PI];
__device__ __align__(16) __nv_bfloat16 g_hhi[(size_t)PNK * PI];
__device__ __align__(16) __nv_bfloat16 g_hlo[(size_t)PNK * PI];

// ---------------- helpers ----------------
__device__ __forceinline__ uint32_t smem_u32(const void* p) {
    return (uint32_t)__cvta_generic_to_shared(p);
}

__device__ __forceinline__ void cpa16(uint32_t dst, const void* src) {
    asm volatile("cp.async.cg.shared.global [%0], [%1], 16;" :: "r"(dst), "l"(src) : "memory");
}
#define CP_COMMIT() asm volatile("cp.async.commit_group;" ::: "memory")
#define CP_WAIT1()  asm volatile("cp.async.wait_group 1;" ::: "memory")
#define CP_WAIT0()  asm volatile("cp.async.wait_group 0;" ::: "memory")

__device__ __forceinline__ void ldsm_x4(uint32_t* r, uint32_t addr) {
    asm volatile("ldmatrix.sync.aligned.m8n8.x4.shared.b16 {%0,%1,%2,%3}, [%4];"
                 : "=r"(r[0]), "=r"(r[1]), "=r"(r[2]), "=r"(r[3]) : "r"(addr) : "memory");
}
__device__ __forceinline__ void ldsm_x2(uint32_t* r, uint32_t addr) {
    asm volatile("ldmatrix.sync.aligned.m8n8.x2.shared.b16 {%0,%1}, [%2];"
                 : "=r"(r[0]), "=r"(r[1]) : "r"(addr) : "memory");
}
__device__ __forceinline__ void mma16816(float* c, const uint32_t* a, const uint32_t* b) {
    asm volatile("mma.sync.aligned.m16n8k16.row.col.f32.bf16.bf16.f32 "
                 "{%0,%1,%2,%3}, {%4,%5,%6,%7}, {%8,%9}, {%0,%1,%2,%3};"
                 : "+f"(c[0]), "+f"(c[1]), "+f"(c[2]), "+f"(c[3])
                 : "r"(a[0]), "r"(a[1]), "r"(a[2]), "r"(a[3]), "r"(b[0]), "r"(b[1])
                 : "memory");
}

__device__ __forceinline__ float silu_f(float g) {
    return g / (1.0f + __expf(-g));
}

// ---------------- routing kernels ----------------
__global__ void k_zero_out(float* out, int n) {
    int i = blockIdx.x * blockDim.x + threadIdx.x;
    int stride = gridDim.x * blockDim.x;
    for (; i < n; i += stride) out[i] = 0.0f;
    if (blockIdx.x == 0 && threadIdx.x < PE) {
        g_counts[threadIdx.x] = 0;
        g_cursor[threadIdx.x] = 0;
    }
}

__global__ void k_count(const int* __restrict__ ids) {
    int i = blockIdx.x * blockDim.x + threadIdx.x;
    if (i < PNK) atomicAdd(&g_counts[ids[i]], 1);
}

__global__ void k_scan() {
    int s = 0;
    for (int e = 0; e < PE; e++) { g_offsets[e] = s; s += g_counts[e]; }
    g_offsets[PE] = s;
}

__global__ void k_scatter(const int* __restrict__ ids, const float* __restrict__ w) {
    int i = blockIdx.x * blockDim.x + threadIdx.x;
    if (i < PNK) {
        int e = ids[i];
        int pos = g_offsets[e] + atomicAdd(&g_cursor[e], 1);
        g_pair_token[pos] = i / PTOPK;
        g_pair_w[pos] = w[i];
    }
}

// ---------------- fp32 -> bf16 hi/lo split ----------------
// Destination globals referenced from DEVICE code only (host-shadow pitfall).
__device__ __forceinline__ void split_body(const float* __restrict__ src,
                                           __nv_bfloat16* __restrict__ hi,
                                           __nv_bfloat16* __restrict__ lo, int n4) {
    int i = blockIdx.x * blockDim.x + threadIdx.x;
    int stride = gridDim.x * blockDim.x;
    for (; i < n4; i += stride) {
        float4 v = reinterpret_cast<const float4*>(src)[i];
        __nv_bfloat162 h0, h1, l0, l1;
        h0.x = __float2bfloat16(v.x); l0.x = __float2bfloat16(v.x - __bfloat162float(h0.x));
        h0.y = __float2bfloat16(v.y); l0.y = __float2bfloat16(v.y - __bfloat162float(h0.y));
        h1.x = __float2bfloat16(v.z); l1.x = __float2bfloat16(v.z - __bfloat162float(h1.x));
        h1.y = __float2bfloat16(v.w); l1.y = __float2bfloat16(v.w - __bfloat162float(h1.y));
        reinterpret_cast<__nv_bfloat162*>(hi)[i * 2 + 0] = h0;
        reinterpret_cast<__nv_bfloat162*>(hi)[i * 2 + 1] = h1;
        reinterpret_cast<__nv_bfloat162*>(lo)[i * 2 + 0] = l0;
        reinterpret_cast<__nv_bfloat162*>(lo)[i * 2 + 1] = l1;
    }
}

__global__ void k_split_x(const float* __restrict__ src) {
    split_body(src, g_xhi, g_xlo, PN * PH / 4);
}
__global__ void k_split_wg(const float* __restrict__ src) {
    split_body(src, g_wghi, g_wglo, PE * PI * PH / 4);
}
__global__ void k_split_wu(const float* __restrict__ src) {
    split_body(src, g_wuhi, g_wulo, PE * PI * PH / 4);
}
__global__ void k_split_wd(const float* __restrict__ src) {
    split_body(src, g_wdhi, g_wdlo, PE * PH * PI / 4);
}

// ============================================================================
// GU kernel: split-bf16 mma.sync, 128 slots x (64 gate + 64 up), BK=32.
// 2-stage cp.async pipeline, dynamic SMEM.
// Per stage (80B rows): A_hi 128x80 @0, A_lo @10240,
//   Bg_hi/Bg_lo/Bu_hi/Bu_lo 64x80 @20480+t*5120.  stage=40960.
// s_tok (128 int) @81920. Total 82432.
// ============================================================================
#define GU_STAGE 40960
#define GU_SMEM  (2 * GU_STAGE + 512)

// stage loaders (explicit, no lambdas)
__device__ __forceinline__ void gu_load_stage(uint32_t sb, const int* s_tok, size_t eoff,
                                              int n0, int k0, int tid) {
#pragma unroll
    for (int it = 0; it < 4; it++) {
        int idx = tid + it * 256;
        int t = idx >> 9;
        int r = (idx >> 2) & 127;
        int c = idx & 3;
        const __nv_bfloat16* src =
            (t ? g_xlo : g_xhi) + (size_t)s_tok[r] * PH + k0 + c * 8;
        cpa16(sb + t * 10240 + r * 80 + c * 16, src);
    }
#pragma unroll
    for (int it = 0; it < 4; it++) {
        int idx = tid + it * 256;
        int t = idx >> 8;          // 0..3
        int r = (idx >> 2) & 63;
        int c = idx & 3;
        const __nv_bfloat16* base;
        if (t == 0) base = g_wghi;
        else if (t == 1) base = g_wglo;
        else if (t == 2) base = g_wuhi;
        else base = g_wulo;
        const __nv_bfloat16* src = base + eoff + (size_t)(n0 + r) * PH + k0 + c * 8;
        cpa16(sb + 20480 + t * 5120 + r * 80 + c * 16, src);
    }
}

__global__ __launch_bounds__(256, 2) void k_gu() {
    extern __shared__ __align__(128) char smem[];
    const int e = blockIdx.z;
    const int beg = g_offsets[e];
    const int end = g_offsets[e + 1];
    const int row0 = beg + blockIdx.x * 128;
    if (row0 >= end) return;
    const int n0 = blockIdx.y * 64;

    const int tid = threadIdx.x;
    const int wid = tid >> 5;
    const int lane = tid & 31;
    const int wr = wid >> 1;   // rows wr*32..+31
    const int wc = wid & 1;    // cols wc*32..+31

    int* s_tok = reinterpret_cast<int*>(smem + 2 * GU_STAGE);
    if (tid < 128) {
        int slot = row0 + tid;
        if (slot >= PNK) slot = PNK - 1;
        s_tok[tid] = g_pair_token[slot];
    }
    __syncthreads();

    const size_t eoff = (size_t)e * PI * PH;

    float accg[2][4][4];
    float accu[2][4][4];
#pragma unroll
    for (int mi = 0; mi < 2; mi++)
#pragma unroll
        for (int ni = 0; ni < 4; ni++)
#pragma unroll
            for (int q = 0; q < 4; q++) { accg[mi][ni][q] = 0.0f; accu[mi][ni][q] = 0.0f; }

    const uint32_t sb0 = smem_u32(smem);
    const uint32_t aHiO = (wr * 32 + (lane & 15)) * 80 + (lane >> 4) * 16;
    const uint32_t bRow = (lane & 7) * 80 + ((lane >> 3) & 1) * 16;
    const uint32_t bgO = 20480 + (wc * 32) * 80 + bRow;

    gu_load_stage(sb0, s_tok, eoff, n0, 0, tid);
    CP_COMMIT();

    const int NC = PH / 32;  // 64
    for (int c = 0; c < NC; c++) {
        if (c + 1 < NC) {
            gu_load_stage(sb0 + ((c + 1) & 1) * GU_STAGE, s_tok, eoff, n0, (c + 1) * 32, tid);
            CP_COMMIT();
            CP_WAIT1();
        } else {
            CP_WAIT0();
        }
        __syncthreads();

        const uint32_t sb = sb0 + (c & 1) * GU_STAGE;
        const uint32_t aHiB = sb + aHiO;
        const uint32_t aLoB = aHiB + 10240;
        const uint32_t bgHiB = sb + bgO;
        const uint32_t bgLoB = bgHiB + 5120;
        const uint32_t buHiB = bgHiB + 10240;
        const uint32_t buLoB = bgHiB + 15360;

#pragma unroll
        for (int ks = 0; ks < 2; ks++) {
            uint32_t ko = ks * 32;
            uint32_t ahi[2][4], alo[2][4];
            ldsm_x4(ahi[0], aHiB + ko);
            ldsm_x4(ahi[1], aHiB + 16 * 80 + ko);
            ldsm_x4(alo[0], aLoB + ko);
            ldsm_x4(alo[1], aLoB + 16 * 80 + ko);
#pragma unroll
            for (int ni = 0; ni < 4; ni++) {
                uint32_t bh[2], bl[2];
                ldsm_x2(bh, bgHiB + ni * 8 * 80 + ko);
                ldsm_x2(bl, bgLoB + ni * 8 * 80 + ko);
#pragma unroll
                for (int mi = 0; mi < 2; mi++) {
                    mma16816(accg[mi][ni], ahi[mi], bh);
                    mma16816(accg[mi][ni], ahi[mi], bl);
                    mma16816(accg[mi][ni], alo[mi], bh);
                }
                ldsm_x2(bh, buHiB + ni * 8 * 80 + ko);
                ldsm_x2(bl, buLoB + ni * 8 * 80 + ko);
#pragma unroll
                for (int mi = 0; mi < 2; mi++) {
                    mma16816(accu[mi][ni], ahi[mi], bh);
                    mma16816(accu[mi][ni], ahi[mi], bl);
                    mma16816(accu[mi][ni], alo[mi], bh);
                }
            }
        }
        __syncthreads();
    }

    // epilogue: h = silu(g)*u, split to bf16 hi/lo
    const int gRow = lane >> 2;
    const int cp2 = (lane & 3) * 2;
#pragma unroll
    for (int mi = 0; mi < 2; mi++) {
#pragma unroll
        for (int ni = 0; ni < 4; ni++) {
            int col = n0 + wc * 32 + ni * 8 + cp2;
            int r0 = wr * 32 + mi * 16 + gRow;
#pragma unroll
            for (int half = 0; half < 2; half++) {
                int slot = row0 + r0 + half * 8;
                if (slot < end) {
                    float g0 = accg[mi][ni][half * 2 + 0];
                    float g1 = accg[mi][ni][half * 2 + 1];
                    float u0 = accu[mi][ni][half * 2 + 0];
                    float u1 = accu[mi][ni][half * 2 + 1];
                    float h0 = silu_f(g0) * u0;
                    float h1 = silu_f(g1) * u1;
                    __nv_bfloat162 vh, vl;
                    vh.x = __float2bfloat16(h0);
                    vl.x = __float2bfloat16(h0 - __bfloat162float(vh.x));
                    vh.y = __float2bfloat16(h1);
                    vl.y = __float2bfloat16(h1 - __bfloat162float(vh.y));
                    *reinterpret_cast<__nv_bfloat162*>(g_hhi + (size_t)slot * PI + col) = vh;
                    *reinterpret_cast<__nv_bfloat162*>(g_hlo + (size_t)slot * PI + col) = vl;
                }
            }
        }
    }
}

// ============================================================================
// Down kernel: 128 slots x 128 H-cols, BK=32 over I. 2-stage cp.async.
// Per stage: A_hi @0, A_lo @10240, B_hi @20480, B_lo @30720. stage=40960.
// s_tok @81920, s_w @82432. Total 82944.
// ============================================================================
#define D_STAGE 40960
#define D_SMEM  (2 * D_STAGE + 1024)

__device__ __forceinline__ void d_load_stage(uint32_t sb, int row0, size_t eoff,
                                             int n0, int k0, int tid) {
#pragma unroll
    for (int it = 0; it < 4; it++) {
        int idx = tid + it * 256;
        int t = idx >> 9;
        int r = (idx >> 2) & 127;
        int c = idx & 3;
        int slot = row0 + r;
        if (slot >= PNK) slot = PNK - 1;
        const __nv_bfloat16* src =
            (t ? g_hlo : g_hhi) + (size_t)slot * PI + k0 + c * 8;
        cpa16(sb + t * 10240 + r * 80 + c * 16, src);
    }
#pragma unroll
    for (int it = 0; it < 4; it++) {
        int idx = tid + it * 256;
        int t = idx >> 9;
        int r = (idx >> 2) & 127;
        int c = idx & 3;
        const __nv_bfloat16* src =
            (t ? g_wdlo : g_wdhi) + eoff + (size_t)(n0 + r) * PI + k0 + c * 8;
        cpa16(sb + 20480 + t * 10240 + r * 80 + c * 16, src);
    }
}

__global__ __launch_bounds__(256, 2) void k_down(float* __restrict__ out) {
    extern __shared__ __align__(128) char smem[];
    const int e = blockIdx.z;
    const int beg = g_offsets[e];
    const int end = g_offsets[e + 1];
    const int row0 = beg + blockIdx.x * 128;
    if (row0 >= end) return;
    const int n0 = blockIdx.y * 128;

    const int tid = threadIdx.x;
    const int wid = tid >> 5;
    const int lane = tid & 31;
    const int wr = wid >> 1;   // rows wr*32..+31
    const int wc = wid & 1;    // cols wc*64..+63

    int* s_tok = reinterpret_cast<int*>(smem + 2 * D_STAGE);
    float* s_w = reinterpret_cast<float*>(smem + 2 * D_STAGE + 512);
    if (tid < 128) {
        int slot = row0 + tid;
        if (slot >= PNK) slot = PNK - 1;
        s_tok[tid] = g_pair_token[slot];
        s_w[tid] = g_pair_w[slot];
    }
    __syncthreads();

    const size_t eoff = (size_t)e * PH * PI;

    float acc[2][8][4];
#pragma unroll
    for (int mi = 0; mi < 2; mi++)
#pragma unroll
        for (int ni = 0; ni < 8; ni++)
#pragma unroll
            for (int q = 0; q < 4; q++) acc[mi][ni][q] = 0.0f;

    const uint32_t sb0 = smem_u32(smem);
    const uint32_t aHiO = (wr * 32 + (lane & 15)) * 80 + (lane >> 4) * 16;
    const uint32_t bRow = (lane & 7) * 80 + ((lane >> 3) & 1) * 16;
    const uint32_t bO = 20480 + (wc * 64) * 80 + bRow;

    d_load_stage(sb0, row0, eoff, n0, 0, tid);
    CP_COMMIT();

    const int NC = PI / 32;  // 44
    for (int c = 0; c < NC; c++) {
        if (c + 1 < NC) {
            d_load_stage(sb0 + ((c + 1) & 1) * D_STAGE, row0, eoff, n0, (c + 1) * 32, tid);
            CP_COMMIT();
            CP_WAIT1();
        } else {
            CP_WAIT0();
        }
        __syncthreads();

        const uint32_t sb = sb0 + (c & 1) * D_STAGE;
        const uint32_t aHiB = sb + aHiO;
        const uint32_t aLoB = aHiB + 10240;
        const uint32_t bHiB = sb + bO;
        const uint32_t bLoB = bHiB + 10240;

#pragma unroll
        for (int ks = 0; ks < 2; ks++) {
            uint32_t ko = ks * 32;
            uint32_t ahi[2][4], alo[2][4];
            ldsm_x4(ahi[0], aHiB + ko);
            ldsm_x4(ahi[1], aHiB + 16 * 80 + ko);
            ldsm_x4(alo[0], aLoB + ko);
            ldsm_x4(alo[1], aLoB + 16 * 80 + ko);
#pragma unroll
            for (int ni = 0; ni < 8; ni++) {
                uint32_t bh[2], bl[2];
                ldsm_x2(bh, bHiB + ni * 8 * 80 + ko);
                ldsm_x2(bl, bLoB + ni * 8 * 80 + ko);
#pragma unroll
                for (int mi = 0; mi < 2; mi++) {
                    mma16816(acc[mi][ni], ahi[mi], bh);
                    mma16816(acc[mi][ni], ahi[mi], bl);
                    mma16816(acc[mi][ni], alo[mi], bh);
                }
            }
        }
        __syncthreads();
    }

    // epilogue: out[token][col] += w * acc
    const int gRow = lane >> 2;
    const int cp2 = (lane & 3) * 2;
#pragma unroll
    for (int mi = 0; mi < 2; mi++) {
#pragma unroll
        for (int ni = 0; ni < 8; ni++) {
            int col = n0 + wc * 64 + ni * 8 + cp2;
            int r0 = wr * 32 + mi * 16 + gRow;
#pragma unroll
            for (int half = 0; half < 2; half++) {
                int lr = r0 + half * 8;
                int slot = row0 + lr;
                if (slot < end) {
                    const int tok = s_tok[lr];
                    const float w = s_w[lr];
                    float* op = out + (size_t)tok * PH + col;
                    atomicAdd(op + 0, w * acc[mi][ni][half * 2 + 0]);
                    atomicAdd(op + 1, w * acc[mi][ni][half * 2 + 1]);
                }
            }
        }
    }
}

// ---------------- launch ----------------
extern "C" void kernel_launch(void* const* d_in, const int* in_sizes, int n_in,
                              void* d_out, int out_size) {
    const float* x = (const float*)d_in[0];          // [N, H]
    const int* topk_ids = (const int*)d_in[1];       // [N, K]
    const float* topk_w = (const float*)d_in[2];     // [N, K]
    const float* Wg = (const float*)d_in[3];         // [E, I, H]
    const float* Wu = (const float*)d_in[4];         // [E, I, H]
    const float* Wd = (const float*)d_in[5];         // [E, H, I]
    float* out = (float*)d_out;                      // [N, H]

    static bool attr_done = false;
    if (!attr_done) {
        cudaFuncSetAttribute(k_gu, cudaFuncAttributeMaxDynamicSharedMemorySize, GU_SMEM);
        cudaFuncSetAttribute(k_down, cudaFuncAttributeMaxDynamicSharedMemorySize, D_SMEM);
        attr_done = true;
    }

    // routing + zero output
    k_zero_out<<<1024, 256>>>(out, PN * PH);
    k_count<<<(PNK + 255) / 256, 256>>>(topk_ids);
    k_scan<<<1, 1>>>();
    k_scatter<<<(PNK + 255) / 256, 256>>>(topk_ids, topk_w);

    // fp32 -> bf16 hi/lo splits (destinations resolved in device code)
    k_split_x<<<4096, 256>>>(x);
    k_split_wg<<<8192, 256>>>(Wg);
    k_split_wu<<<8192, 256>>>(Wu);
    k_split_wd<<<8192, 256>>>(Wd);

    // gate/up GEMM + SwiGLU -> hidden hi/lo
    {
        dim3 grid(PN / 128, PI / 64, PE);    // 32 x 22 x 8
        k_gu<<<grid, 256, GU_SMEM>>>();
    }
    // down GEMM -> weighted atomic combine into out
    {
        dim3 grid(PN / 128, PH / 128, PE);   // 32 x 16 x 8
        k_down<<<grid, 256, D_SMEM>>>(out);
    }
}

// round 9
// speedup vs baseline: 2.8096x; 1.2317x over previous
#include <cuda_runtime.h>
#include <cuda_bf16.h>
#include <cstdint>

// Problem constants
#define PN 4096
#define PTOPK 2
#define PE 8
#define PH 2048
#define PI 1408
#define PNK (PN * PTOPK)   // 8192

// ---------------- device scratch ----------------
__device__ int g_counts[PE];
__device__ int g_offsets[PE + 1];
__device__ int g_cursor[PE];
__device__ int g_pair_token[PNK];
__device__ float g_pair_w[PNK];

__device__ __align__(16) __nv_bfloat16 g_xhi[(size_t)PN * PH];
__device__ __align__(16) __nv_bfloat16 g_xlo[(size_t)PN * PH];
__device__ __align__(16) __nv_bfloat16 g_wghi[(size_t)PE * PI * PH];
__device__ __align__(16) __nv_bfloat16 g_wglo[(size_t)PE * PI * PH];
__device__ __align__(16) __nv_bfloat16 g_wuhi[(size_t)PE * PI * PH];
__device__ __align__(16) __nv_bfloat16 g_wulo[(size_t)PE * PI * PH];
__device__ __align__(16) __nv_bfloat16 g_wdhi[(size_t)PE * PH * PI];
__device__ __align__(16) __nv_bfloat16 g_wdlo[(size_t)PE * PH * PI];
__device__ __align__(16) __nv_bfloat16 g_hhi[(size_t)PNK * PI];
__device__ __align__(16) __nv_bfloat16 g_hlo[(size_t)PNK * PI];

// ---------------- helpers ----------------
__device__ __forceinline__ uint32_t smem_u32(const void* p) {
    return (uint32_t)__cvta_generic_to_shared(p);
}

__device__ __forceinline__ void cpa16(uint32_t dst, const void* src) {
    asm volatile("cp.async.cg.shared.global [%0], [%1], 16;" :: "r"(dst), "l"(src) : "memory");
}
#define CP_COMMIT() asm volatile("cp.async.commit_group;" ::: "memory")
#define CP_WAIT1()  asm volatile("cp.async.wait_group 1;" ::: "memory")

__device__ __forceinline__ void ldsm_x4(uint32_t* r, uint32_t addr) {
    asm volatile("ldmatrix.sync.aligned.m8n8.x4.shared.b16 {%0,%1,%2,%3}, [%4];"
                 : "=r"(r[0]), "=r"(r[1]), "=r"(r[2]), "=r"(r[3]) : "r"(addr) : "memory");
}
__device__ __forceinline__ void mma16816(float* c, const uint32_t* a, const uint32_t* b) {
    asm volatile("mma.sync.aligned.m16n8k16.row.col.f32.bf16.bf16.f32 "
                 "{%0,%1,%2,%3}, {%4,%5,%6,%7}, {%8,%9}, {%0,%1,%2,%3};"
                 : "+f"(c[0]), "+f"(c[1]), "+f"(c[2]), "+f"(c[3])
                 : "r"(a[0]), "r"(a[1]), "r"(a[2]), "r"(a[3]), "r"(b[0]), "r"(b[1])
                 : "memory");
}

__device__ __forceinline__ float silu_f(float g) {
    return g / (1.0f + __expf(-g));
}

// 64B-pitch XOR swizzle: row r, 16B-chunk c (0..3). Conflict-free for
// cp.async stores and all ldmatrix phases (8 distinct addrs mod 128B).
#define SWO(r, c) ((uint32_t)((r) * 64 + ((((c) ^ (((r) >> 1) & 3))) * 16)))

// ---------------- routing kernels ----------------
__global__ void k_zero_out(float* out, int n) {
    int i = blockIdx.x * blockDim.x + threadIdx.x;
    int stride = gridDim.x * blockDim.x;
    for (; i < n; i += stride) out[i] = 0.0f;
    if (blockIdx.x == 0 && threadIdx.x < PE) {
        g_counts[threadIdx.x] = 0;
        g_cursor[threadIdx.x] = 0;
    }
}

__global__ void k_count(const int* __restrict__ ids) {
    int i = blockIdx.x * blockDim.x + threadIdx.x;
    if (i < PNK) atomicAdd(&g_counts[ids[i]], 1);
}

__global__ void k_scan() {
    int s = 0;
    for (int e = 0; e < PE; e++) { g_offsets[e] = s; s += g_counts[e]; }
    g_offsets[PE] = s;
}

__global__ void k_scatter(const int* __restrict__ ids, const float* __restrict__ w) {
    int i = blockIdx.x * blockDim.x + threadIdx.x;
    if (i < PNK) {
        int e = ids[i];
        int pos = g_offsets[e] + atomicAdd(&g_cursor[e], 1);
        g_pair_token[pos] = i / PTOPK;
        g_pair_w[pos] = w[i];
    }
}

// ---------------- fp32 -> bf16 hi/lo split ----------------
// Destination globals referenced from DEVICE code only (host-shadow pitfall).
__device__ __forceinline__ void split_body(const float* __restrict__ src,
                                           __nv_bfloat16* __restrict__ hi,
                                           __nv_bfloat16* __restrict__ lo, int n4) {
    int i = blockIdx.x * blockDim.x + threadIdx.x;
    int stride = gridDim.x * blockDim.x;
    for (; i < n4; i += stride) {
        float4 v = reinterpret_cast<const float4*>(src)[i];
        __nv_bfloat162 h0, h1, l0, l1;
        h0.x = __float2bfloat16(v.x); l0.x = __float2bfloat16(v.x - __bfloat162float(h0.x));
        h0.y = __float2bfloat16(v.y); l0.y = __float2bfloat16(v.y - __bfloat162float(h0.y));
        h1.x = __float2bfloat16(v.z); l1.x = __float2bfloat16(v.z - __bfloat162float(h1.x));
        h1.y = __float2bfloat16(v.w); l1.y = __float2bfloat16(v.w - __bfloat162float(h1.y));
        reinterpret_cast<__nv_bfloat162*>(hi)[i * 2 + 0] = h0;
        reinterpret_cast<__nv_bfloat162*>(hi)[i * 2 + 1] = h1;
        reinterpret_cast<__nv_bfloat162*>(lo)[i * 2 + 0] = l0;
        reinterpret_cast<__nv_bfloat162*>(lo)[i * 2 + 1] = l1;
    }
}

__global__ void k_split_x(const float* __restrict__ src) {
    split_body(src, g_xhi, g_xlo, PN * PH / 4);
}
__global__ void k_split_wg(const float* __restrict__ src) {
    split_body(src, g_wghi, g_wglo, PE * PI * PH / 4);
}
__global__ void k_split_wu(const float* __restrict__ src) {
    split_body(src, g_wuhi, g_wulo, PE * PI * PH / 4);
}
__global__ void k_split_wd(const float* __restrict__ src) {
    split_body(src, g_wdhi, g_wdlo, PE * PH * PI / 4);
}

// ============================================================================
// GU kernel: split-bf16 mma.sync, 128 slots x (64 gate + 64 up), BK=32.
// 3-stage cp.async pipeline, 64B-pitch XOR swizzle, one barrier per chunk.
// Stage (32768 B): A_hi @0, A_lo @8192, Bg_hi @16384, Bg_lo @20480,
//                  Bu_hi @24576, Bu_lo @28672.
// s_tok @98304. Total 98816.
// ============================================================================
#define GU_STAGE 32768
#define GU_SMEM  (3 * GU_STAGE + 512)

__device__ __forceinline__ void gu_load_stage(uint32_t sb, const int* s_tok, size_t eoff,
                                              int n0, int k0, int tid) {
#pragma unroll
    for (int it = 0; it < 4; it++) {
        int idx = tid + it * 256;
        int t = idx >> 9;
        int r = (idx >> 2) & 127;
        int c = idx & 3;
        const __nv_bfloat16* src =
            (t ? g_xlo : g_xhi) + (size_t)s_tok[r] * PH + k0 + c * 8;
        cpa16(sb + t * 8192 + SWO(r, c), src);
    }
#pragma unroll
    for (int it = 0; it < 4; it++) {
        int idx = tid + it * 256;
        int t = idx >> 8;          // 0..3
        int r = (idx >> 2) & 63;
        int c = idx & 3;
        const __nv_bfloat16* base;
        if (t == 0) base = g_wghi;
        else if (t == 1) base = g_wglo;
        else if (t == 2) base = g_wuhi;
        else base = g_wulo;
        const __nv_bfloat16* src = base + eoff + (size_t)(n0 + r) * PH + k0 + c * 8;
        cpa16(sb + 16384 + t * 4096 + SWO(r, c), src);
    }
}

__global__ __launch_bounds__(256, 2) void k_gu() {
    extern __shared__ __align__(128) char smem[];
    const int e = blockIdx.z;
    const int beg = g_offsets[e];
    const int end = g_offsets[e + 1];
    const int row0 = beg + blockIdx.x * 128;
    if (row0 >= end) return;
    const int n0 = blockIdx.y * 64;

    const int tid = threadIdx.x;
    const int wid = tid >> 5;
    const int lane = tid & 31;
    const int wr = wid >> 1;   // rows wr*32..+31
    const int wc = wid & 1;    // cols wc*32..+31

    int* s_tok = reinterpret_cast<int*>(smem + 3 * GU_STAGE);
    if (tid < 128) {
        int slot = row0 + tid;
        if (slot >= PNK) slot = PNK - 1;
        s_tok[tid] = g_pair_token[slot];
    }
    __syncthreads();

    const size_t eoff = (size_t)e * PI * PH;

    float accg[2][4][4];
    float accu[2][4][4];
#pragma unroll
    for (int mi = 0; mi < 2; mi++)
#pragma unroll
        for (int ni = 0; ni < 4; ni++)
#pragma unroll
            for (int q = 0; q < 4; q++) { accg[mi][ni][q] = 0.0f; accu[mi][ni][q] = 0.0f; }

    const uint32_t sb0 = smem_u32(smem);

    // per-lane relative ldsm offsets (within a stage)
    uint32_t offA[2][2], offB[2][2];
    {
        const int rA = wr * 32 + (lane & 15);
        const int cA = lane >> 4;
#pragma unroll
        for (int mi = 0; mi < 2; mi++)
#pragma unroll
            for (int ks = 0; ks < 2; ks++)
                offA[mi][ks] = SWO(rA + mi * 16, cA + 2 * ks);
        const int rB = (lane & 7) + 8 * ((lane >> 4) & 1);
        const int cB = (lane >> 3) & 1;
#pragma unroll
        for (int h = 0; h < 2; h++)
#pragma unroll
            for (int ks = 0; ks < 2; ks++)
                offB[h][ks] = SWO(wc * 32 + 16 * h + rB, cB + 2 * ks);
    }

    gu_load_stage(sb0, s_tok, eoff, n0, 0, tid);
    CP_COMMIT();
    gu_load_stage(sb0 + GU_STAGE, s_tok, eoff, n0, 32, tid);
    CP_COMMIT();

    const int NC = PH / 32;  // 64
    int cb = 0, lb = 2;
    for (int c = 0; c < NC; c++) {
        CP_WAIT1();
        __syncthreads();
        if (c + 2 < NC)
            gu_load_stage(sb0 + lb * GU_STAGE, s_tok, eoff, n0, (c + 2) * 32, tid);
        CP_COMMIT();

        const uint32_t sb = sb0 + cb * GU_STAGE;
#pragma unroll
        for (int ks = 0; ks < 2; ks++) {
            uint32_t ahi[2][4], alo[2][4];
            ldsm_x4(ahi[0], sb + offA[0][ks]);
            ldsm_x4(ahi[1], sb + offA[1][ks]);
            ldsm_x4(alo[0], sb + 8192 + offA[0][ks]);
            ldsm_x4(alo[1], sb + 8192 + offA[1][ks]);
            {   // gate
                uint32_t bh[8], bl[8];
                ldsm_x4(bh + 0, sb + 16384 + offB[0][ks]);
                ldsm_x4(bh + 4, sb + 16384 + offB[1][ks]);
                ldsm_x4(bl + 0, sb + 20480 + offB[0][ks]);
                ldsm_x4(bl + 4, sb + 20480 + offB[1][ks]);
#pragma unroll
                for (int ni = 0; ni < 4; ni++) {
                    const uint32_t* ph = &bh[(ni >> 1) * 4 + (ni & 1) * 2];
                    const uint32_t* pl = &bl[(ni >> 1) * 4 + (ni & 1) * 2];
#pragma unroll
                    for (int mi = 0; mi < 2; mi++) {
                        mma16816(accg[mi][ni], ahi[mi], ph);
                        mma16816(accg[mi][ni], ahi[mi], pl);
                        mma16816(accg[mi][ni], alo[mi], ph);
                    }
                }
            }
            {   // up
                uint32_t bh[8], bl[8];
                ldsm_x4(bh + 0, sb + 24576 + offB[0][ks]);
                ldsm_x4(bh + 4, sb + 24576 + offB[1][ks]);
                ldsm_x4(bl + 0, sb + 28672 + offB[0][ks]);
                ldsm_x4(bl + 4, sb + 28672 + offB[1][ks]);
#pragma unroll
                for (int ni = 0; ni < 4; ni++) {
                    const uint32_t* ph = &bh[(ni >> 1) * 4 + (ni & 1) * 2];
                    const uint32_t* pl = &bl[(ni >> 1) * 4 + (ni & 1) * 2];
#pragma unroll
                    for (int mi = 0; mi < 2; mi++) {
                        mma16816(accu[mi][ni], ahi[mi], ph);
                        mma16816(accu[mi][ni], ahi[mi], pl);
                        mma16816(accu[mi][ni], alo[mi], ph);
                    }
                }
            }
        }
        cb = (cb == 2) ? 0 : cb + 1;
        lb = (lb == 2) ? 0 : lb + 1;
    }

    // epilogue: h = silu(g)*u, split to bf16 hi/lo
    const int gRow = lane >> 2;
    const int cp2 = (lane & 3) * 2;
#pragma unroll
    for (int mi = 0; mi < 2; mi++) {
#pragma unroll
        for (int ni = 0; ni < 4; ni++) {
            int col = n0 + wc * 32 + ni * 8 + cp2;
            int r0 = wr * 32 + mi * 16 + gRow;
#pragma unroll
            for (int half = 0; half < 2; half++) {
                int slot = row0 + r0 + half * 8;
                if (slot < end) {
                    float g0 = accg[mi][ni][half * 2 + 0];
                    float g1 = accg[mi][ni][half * 2 + 1];
                    float u0 = accu[mi][ni][half * 2 + 0];
                    float u1 = accu[mi][ni][half * 2 + 1];
                    float h0 = silu_f(g0) * u0;
                    float h1 = silu_f(g1) * u1;
                    __nv_bfloat162 vh, vl;
                    vh.x = __float2bfloat16(h0);
                    vl.x = __float2bfloat16(h0 - __bfloat162float(vh.x));
                    vh.y = __float2bfloat16(h1);
                    vl.y = __float2bfloat16(h1 - __bfloat162float(vh.y));
                    *reinterpret_cast<__nv_bfloat162*>(g_hhi + (size_t)slot * PI + col) = vh;
                    *reinterpret_cast<__nv_bfloat162*>(g_hlo + (size_t)slot * PI + col) = vl;
                }
            }
        }
    }
}

// ============================================================================
// Down kernel: 128 slots x 128 H-cols, BK=32 over I. 3-stage pipeline.
// Stage (32768 B): A_hi @0, A_lo @8192, B_hi @16384, B_lo @24576.
// s_tok @98304, s_w @98816. Total 99328.
// ============================================================================
#define D_STAGE 32768
#define D_SMEM  (3 * D_STAGE + 1024)

__device__ __forceinline__ void d_load_stage(uint32_t sb, int row0, size_t eoff,
                                             int n0, int k0, int tid) {
#pragma unroll
    for (int it = 0; it < 4; it++) {
        int idx = tid + it * 256;
        int t = idx >> 9;
        int r = (idx >> 2) & 127;
        int c = idx & 3;
        int slot = row0 + r;
        if (slot >= PNK) slot = PNK - 1;
        const __nv_bfloat16* src =
            (t ? g_hlo : g_hhi) + (size_t)slot * PI + k0 + c * 8;
        cpa16(sb + t * 8192 + SWO(r, c), src);
    }
#pragma unroll
    for (int it = 0; it < 4; it++) {
        int idx = tid + it * 256;
        int t = idx >> 9;
        int r = (idx >> 2) & 127;
        int c = idx & 3;
        const __nv_bfloat16* src =
            (t ? g_wdlo : g_wdhi) + eoff + (size_t)(n0 + r) * PI + k0 + c * 8;
        cpa16(sb + 16384 + t * 8192 + SWO(r, c), src);
    }
}

__global__ __launch_bounds__(256, 2) void k_down(float* __restrict__ out) {
    extern __shared__ __align__(128) char smem[];
    const int e = blockIdx.z;
    const int beg = g_offsets[e];
    const int end = g_offsets[e + 1];
    const int row0 = beg + blockIdx.x * 128;
    if (row0 >= end) return;
    const int n0 = blockIdx.y * 128;

    const int tid = threadIdx.x;
    const int wid = tid >> 5;
    const int lane = tid & 31;
    const int wr = wid >> 1;   // rows wr*32..+31
    const int wc = wid & 1;    // cols wc*64..+63

    int* s_tok = reinterpret_cast<int*>(smem + 3 * D_STAGE);
    float* s_w = reinterpret_cast<float*>(smem + 3 * D_STAGE + 512);
    if (tid < 128) {
        int slot = row0 + tid;
        if (slot >= PNK) slot = PNK - 1;
        s_tok[tid] = g_pair_token[slot];
        s_w[tid] = g_pair_w[slot];
    }
    __syncthreads();

    const size_t eoff = (size_t)e * PH * PI;

    float acc[2][8][4];
#pragma unroll
    for (int mi = 0; mi < 2; mi++)
#pragma unroll
        for (int ni = 0; ni < 8; ni++)
#pragma unroll
            for (int q = 0; q < 4; q++) acc[mi][ni][q] = 0.0f;

    const uint32_t sb0 = smem_u32(smem);

    uint32_t offA[2][2], offB[4][2];
    {
        const int rA = wr * 32 + (lane & 15);
        const int cA = lane >> 4;
#pragma unroll
        for (int mi = 0; mi < 2; mi++)
#pragma unroll
            for (int ks = 0; ks < 2; ks++)
                offA[mi][ks] = SWO(rA + mi * 16, cA + 2 * ks);
        const int rB = (lane & 7) + 8 * ((lane >> 4) & 1);
        const int cB = (lane >> 3) & 1;
#pragma unroll
        for (int h = 0; h < 4; h++)
#pragma unroll
            for (int ks = 0; ks < 2; ks++)
                offB[h][ks] = SWO(wc * 64 + 16 * h + rB, cB + 2 * ks);
    }

    d_load_stage(sb0, row0, eoff, n0, 0, tid);
    CP_COMMIT();
    d_load_stage(sb0 + D_STAGE, row0, eoff, n0, 32, tid);
    CP_COMMIT();

    const int NC = PI / 32;  // 44
    int cb = 0, lb = 2;
    for (int c = 0; c < NC; c++) {
        CP_WAIT1();
        __syncthreads();
        if (c + 2 < NC)
            d_load_stage(sb0 + lb * D_STAGE, row0, eoff, n0, (c + 2) * 32, tid);
        CP_COMMIT();

        const uint32_t sb = sb0 + cb * D_STAGE;
#pragma unroll
        for (int ks = 0; ks < 2; ks++) {
            uint32_t ahi[2][4], alo[2][4];
            ldsm_x4(ahi[0], sb + offA[0][ks]);
            ldsm_x4(ahi[1], sb + offA[1][ks]);
            ldsm_x4(alo[0], sb + 8192 + offA[0][ks]);
            ldsm_x4(alo[1], sb + 8192 + offA[1][ks]);
#pragma unroll
            for (int h = 0; h < 4; h++) {
                uint32_t bh[4], bl[4];
                ldsm_x4(bh, sb + 16384 + offB[h][ks]);
                ldsm_x4(bl, sb + 24576 + offB[h][ks]);
#pragma unroll
                for (int sub = 0; sub < 2; sub++) {
                    int ni = h * 2 + sub;
                    const uint32_t* ph = &bh[sub * 2];
                    const uint32_t* pl = &bl[sub * 2];
#pragma unroll
                    for (int mi = 0; mi < 2; mi++) {
                        mma16816(acc[mi][ni], ahi[mi], ph);
                        mma16816(acc[mi][ni], ahi[mi], pl);
                        mma16816(acc[mi][ni], alo[mi], ph);
                    }
                }
            }
        }
        cb = (cb == 2) ? 0 : cb + 1;
        lb = (lb == 2) ? 0 : lb + 1;
    }

    // epilogue: out[token][col] += w * acc
    const int gRow = lane >> 2;
    const int cp2 = (lane & 3) * 2;
#pragma unroll
    for (int mi = 0; mi < 2; mi++) {
#pragma unroll
        for (int ni = 0; ni < 8; ni++) {
            int col = n0 + wc * 64 + ni * 8 + cp2;
            int r0 = wr * 32 + mi * 16 + gRow;
#pragma unroll
            for (int half = 0; half < 2; half++) {
                int lr = r0 + half * 8;
                int slot = row0 + lr;
                if (slot < end) {
                    const int tok = s_tok[lr];
                    const float w = s_w[lr];
                    float* op = out + (size_t)tok * PH + col;
                    atomicAdd(op + 0, w * acc[mi][ni][half * 2 + 0]);
                    atomicAdd(op + 1, w * acc[mi][ni][half * 2 + 1]);
                }
            }
        }
    }
}

// ---------------- launch ----------------
extern "C" void kernel_launch(void* const* d_in, const int* in_sizes, int n_in,
                              void* d_out, int out_size) {
    const float* x = (const float*)d_in[0];          // [N, H]
    const int* topk_ids = (const int*)d_in[1];       // [N, K]
    const float* topk_w = (const float*)d_in[2];     // [N, K]
    const float* Wg = (const float*)d_in[3];         // [E, I, H]
    const float* Wu = (const float*)d_in[4];         // [E, I, H]
    const float* Wd = (const float*)d_in[5];         // [E, H, I]
    float* out = (float*)d_out;                      // [N, H]

    static bool attr_done = false;
    if (!attr_done) {
        cudaFuncSetAttribute(k_gu, cudaFuncAttributeMaxDynamicSharedMemorySize, GU_SMEM);
        cudaFuncSetAttribute(k_down, cudaFuncAttributeMaxDynamicSharedMemorySize, D_SMEM);
        attr_done = true;
    }

    // routing + zero output
    k_zero_out<<<1024, 256>>>(out, PN * PH);
    k_count<<<(PNK + 255) / 256, 256>>>(topk_ids);
    k_scan<<<1, 1>>>();
    k_scatter<<<(PNK + 255) / 256, 256>>>(topk_ids, topk_w);

    // fp32 -> bf16 hi/lo splits (destinations resolved in device code)
    k_split_x<<<4096, 256>>>(x);
    k_split_wg<<<8192, 256>>>(Wg);
    k_split_wu<<<8192, 256>>>(Wu);
    k_split_wd<<<8192, 256>>>(Wd);

    // gate/up GEMM + SwiGLU -> hidden hi/lo
    {
        dim3 grid(PN / 128, PI / 64, PE);    // 32 x 22 x 8
        k_gu<<<grid, 256, GU_SMEM>>>();
    }
    // down GEMM -> weighted atomic combine into out
    {
        dim3 grid(PN / 128, PH / 128, PE);   // 32 x 16 x 8
        k_down<<<grid, 256, D_SMEM>>>(out);
    }
}

// round 11
// speedup vs baseline: 2.8287x; 1.0068x over previous
#include <cuda_runtime.h>
#include <cuda_bf16.h>
#include <cstdint>

// Problem constants
#define PN 4096
#define PTOPK 2
#define PE 8
#define PH 2048
#define PI 1408
#define PNK (PN * PTOPK)   // 8192

// ---------------- device scratch ----------------
__device__ int g_offsets[PE + 1];
__device__ int g_pair_token[PNK];
__device__ int g_pair_slot[PNK];

__device__ __align__(16) __nv_bfloat16 g_xhi[(size_t)PN * PH];
__device__ __align__(16) __nv_bfloat16 g_xlo[(size_t)PN * PH];
__device__ __align__(16) __nv_bfloat16 g_wghi[(size_t)PE * PI * PH];
__device__ __align__(16) __nv_bfloat16 g_wglo[(size_t)PE * PI * PH];
__device__ __align__(16) __nv_bfloat16 g_wuhi[(size_t)PE * PI * PH];
__device__ __align__(16) __nv_bfloat16 g_wulo[(size_t)PE * PI * PH];
__device__ __align__(16) __nv_bfloat16 g_wdhi[(size_t)PE * PH * PI];
__device__ __align__(16) __nv_bfloat16 g_wdlo[(size_t)PE * PH * PI];
__device__ __align__(16) __nv_bfloat16 g_hhi[(size_t)PNK * PI];
__device__ __align__(16) __nv_bfloat16 g_hlo[(size_t)PNK * PI];
__device__ __align__(16) float g_y[(size_t)PNK * PH];

// ---------------- helpers ----------------
__device__ __forceinline__ uint32_t smem_u32(const void* p) {
    return (uint32_t)__cvta_generic_to_shared(p);
}

__device__ __forceinline__ void cpa16(uint32_t dst, const void* src) {
    asm volatile("cp.async.cg.shared.global [%0], [%1], 16;" :: "r"(dst), "l"(src) : "memory");
}
#define CP_COMMIT() asm volatile("cp.async.commit_group;" ::: "memory")
#define CP_WAIT1()  asm volatile("cp.async.wait_group 1;" ::: "memory")

__device__ __forceinline__ void ldsm_x4(uint32_t* r, uint32_t addr) {
    asm volatile("ldmatrix.sync.aligned.m8n8.x4.shared.b16 {%0,%1,%2,%3}, [%4];"
                 : "=r"(r[0]), "=r"(r[1]), "=r"(r[2]), "=r"(r[3]) : "r"(addr) : "memory");
}
__device__ __forceinline__ void mma16816(float* c, const uint32_t* a, const uint32_t* b) {
    asm volatile("mma.sync.aligned.m16n8k16.row.col.f32.bf16.bf16.f32 "
                 "{%0,%1,%2,%3}, {%4,%5,%6,%7}, {%8,%9}, {%0,%1,%2,%3};"
                 : "+f"(c[0]), "+f"(c[1]), "+f"(c[2]), "+f"(c[3])
                 : "r"(a[0]), "r"(a[1]), "r"(a[2]), "r"(a[3]), "r"(b[0]), "r"(b[1])
                 : "memory");
}

__device__ __forceinline__ float silu_f(float g) {
    return g / (1.0f + __expf(-g));
}

// 64B-pitch XOR swizzle: row r, 16B-chunk c (0..3). Conflict-free for
// cp.async stores and all ldmatrix phases.
#define SWO(r, c) ((uint32_t)((r) * 64 + ((((c) ^ (((r) >> 1) & 3))) * 16)))

// ---------------- routing: ONE single-CTA kernel ----------------
__global__ void k_route(const int* __restrict__ ids) {
    __shared__ int cnt[PE];
    __shared__ int off[PE + 1];
    __shared__ int cur[PE];
    const int tid = threadIdx.x;
    if (tid < PE) { cnt[tid] = 0; cur[tid] = 0; }
    __syncthreads();
    for (int i = tid; i < PNK; i += 256) atomicAdd(&cnt[ids[i]], 1);
    __syncthreads();
    if (tid == 0) {
        int s = 0;
        for (int e = 0; e < PE; e++) { off[e] = s; g_offsets[e] = s; s += cnt[e]; }
        off[PE] = s;
        g_offsets[PE] = s;
    }
    __syncthreads();
    for (int i = tid; i < PNK; i += 256) {
        int e = ids[i];
        int pos = off[e] + atomicAdd(&cur[e], 1);
        g_pair_token[pos] = i / PTOPK;
        g_pair_slot[i] = pos;
    }
}

// ---------------- fp32 -> bf16 hi/lo split ----------------
// Destination globals referenced from DEVICE code only (host-shadow pitfall).
__device__ __forceinline__ void split_body(const float* __restrict__ src,
                                           __nv_bfloat16* __restrict__ hi,
                                           __nv_bfloat16* __restrict__ lo, int n4) {
    int i = blockIdx.x * blockDim.x + threadIdx.x;
    int stride = gridDim.x * blockDim.x;
    for (; i < n4; i += stride) {
        float4 v = reinterpret_cast<const float4*>(src)[i];
        __nv_bfloat162 h0, h1, l0, l1;
        h0.x = __float2bfloat16(v.x); l0.x = __float2bfloat16(v.x - __bfloat162float(h0.x));
        h0.y = __float2bfloat16(v.y); l0.y = __float2bfloat16(v.y - __bfloat162float(h0.y));
        h1.x = __float2bfloat16(v.z); l1.x = __float2bfloat16(v.z - __bfloat162float(h1.x));
        h1.y = __float2bfloat16(v.w); l1.y = __float2bfloat16(v.w - __bfloat162float(h1.y));
        reinterpret_cast<__nv_bfloat162*>(hi)[i * 2 + 0] = h0;
        reinterpret_cast<__nv_bfloat162*>(hi)[i * 2 + 1] = h1;
        reinterpret_cast<__nv_bfloat162*>(lo)[i * 2 + 0] = l0;
        reinterpret_cast<__nv_bfloat162*>(lo)[i * 2 + 1] = l1;
    }
}

__global__ void k_split_x(const float* __restrict__ src) {
    split_body(src, g_xhi, g_xlo, PN * PH / 4);
}
__global__ void k_split_wg(const float* __restrict__ src) {
    split_body(src, g_wghi, g_wglo, PE * PI * PH / 4);
}
__global__ void k_split_wu(const float* __restrict__ src) {
    split_body(src, g_wuhi, g_wulo, PE * PI * PH / 4);
}
__global__ void k_split_wd(const float* __restrict__ src) {
    split_body(src, g_wdhi, g_wdlo, PE * PH * PI / 4);
}

// ============================================================================
// GU kernel: split-bf16 mma.sync, 128 slots x (64 gate + 64 up), BK=32.
// 3-stage cp.async pipeline, 64B-pitch XOR swizzle, one barrier per chunk.
// ============================================================================
#define GU_STAGE 32768
#define GU_SMEM  (3 * GU_STAGE + 512)

__device__ __forceinline__ void gu_load_stage(uint32_t sb, const int* s_tok, size_t eoff,
                                              int n0, int k0, int tid) {
#pragma unroll
    for (int it = 0; it < 4; it++) {
        int idx = tid + it * 256;
        int t = idx >> 9;
        int r = (idx >> 2) & 127;
        int c = idx & 3;
        const __nv_bfloat16* src =
            (t ? g_xlo : g_xhi) + (size_t)s_tok[r] * PH + k0 + c * 8;
        cpa16(sb + t * 8192 + SWO(r, c), src);
    }
#pragma unroll
    for (int it = 0; it < 4; it++) {
        int idx = tid + it * 256;
        int t = idx >> 8;          // 0..3
        int r = (idx >> 2) & 63;
        int c = idx & 3;
        const __nv_bfloat16* base;
        if (t == 0) base = g_wghi;
        else if (t == 1) base = g_wglo;
        else if (t == 2) base = g_wuhi;
        else base = g_wulo;
        const __nv_bfloat16* src = base + eoff + (size_t)(n0 + r) * PH + k0 + c * 8;
        cpa16(sb + 16384 + t * 4096 + SWO(r, c), src);
    }
}

__global__ __launch_bounds__(256, 2) void k_gu() {
    extern __shared__ __align__(128) char smem[];
    const int e = blockIdx.z;
    const int beg = g_offsets[e];
    const int end = g_offsets[e + 1];
    const int row0 = beg + blockIdx.x * 128;
    if (row0 >= end) return;
    const int n0 = blockIdx.y * 64;

    const int tid = threadIdx.x;
    const int wid = tid >> 5;
    const int lane = tid & 31;
    const int wr = wid >> 1;   // rows wr*32..+31
    const int wc = wid & 1;    // cols wc*32..+31

    int* s_tok = reinterpret_cast<int*>(smem + 3 * GU_STAGE);
    if (tid < 128) {
        int slot = row0 + tid;
        if (slot >= PNK) slot = PNK - 1;
        s_tok[tid] = g_pair_token[slot];
    }
    __syncthreads();

    const size_t eoff = (size_t)e * PI * PH;

    float accg[2][4][4];
    float accu[2][4][4];
#pragma unroll
    for (int mi = 0; mi < 2; mi++)
#pragma unroll
        for (int ni = 0; ni < 4; ni++)
#pragma unroll
            for (int q = 0; q < 4; q++) { accg[mi][ni][q] = 0.0f; accu[mi][ni][q] = 0.0f; }

    const uint32_t sb0 = smem_u32(smem);

    uint32_t offA[2][2], offB[2][2];
    {
        const int rA = wr * 32 + (lane & 15);
        const int cA = lane >> 4;
#pragma unroll
        for (int mi = 0; mi < 2; mi++)
#pragma unroll
            for (int ks = 0; ks < 2; ks++)
                offA[mi][ks] = SWO(rA + mi * 16, cA + 2 * ks);
        const int rB = (lane & 7) + 8 * ((lane >> 4) & 1);
        const int cB = (lane >> 3) & 1;
#pragma unroll
        for (int h = 0; h < 2; h++)
#pragma unroll
            for (int ks = 0; ks < 2; ks++)
                offB[h][ks] = SWO(wc * 32 + 16 * h + rB, cB + 2 * ks);
    }

    gu_load_stage(sb0, s_tok, eoff, n0, 0, tid);
    CP_COMMIT();
    gu_load_stage(sb0 + GU_STAGE, s_tok, eoff, n0, 32, tid);
    CP_COMMIT();

    const int NC = PH / 32;  // 64
    int cb = 0, lb = 2;
    for (int c = 0; c < NC; c++) {
        CP_WAIT1();
        __syncthreads();
        if (c + 2 < NC)
            gu_load_stage(sb0 + lb * GU_STAGE, s_tok, eoff, n0, (c + 2) * 32, tid);
        CP_COMMIT();

        const uint32_t sb = sb0 + cb * GU_STAGE;
#pragma unroll
        for (int ks = 0; ks < 2; ks++) {
            uint32_t ahi[2][4], alo[2][4];
            ldsm_x4(ahi[0], sb + offA[0][ks]);
            ldsm_x4(ahi[1], sb + offA[1][ks]);
            ldsm_x4(alo[0], sb + 8192 + offA[0][ks]);
            ldsm_x4(alo[1], sb + 8192 + offA[1][ks]);
            {   // gate
                uint32_t bh[8], bl[8];
                ldsm_x4(bh + 0, sb + 16384 + offB[0][ks]);
                ldsm_x4(bh + 4, sb + 16384 + offB[1][ks]);
                ldsm_x4(bl + 0, sb + 20480 + offB[0][ks]);
                ldsm_x4(bl + 4, sb + 20480 + offB[1][ks]);
#pragma unroll
                for (int ni = 0; ni < 4; ni++) {
                    const uint32_t* ph = &bh[(ni >> 1) * 4 + (ni & 1) * 2];
                    const uint32_t* pl = &bl[(ni >> 1) * 4 + (ni & 1) * 2];
#pragma unroll
                    for (int mi = 0; mi < 2; mi++) {
                        mma16816(accg[mi][ni], ahi[mi], ph);
                        mma16816(accg[mi][ni], ahi[mi], pl);
                        mma16816(accg[mi][ni], alo[mi], ph);
                    }
                }
            }
            {   // up
                uint32_t bh[8], bl[8];
                ldsm_x4(bh + 0, sb + 24576 + offB[0][ks]);
                ldsm_x4(bh + 4, sb + 24576 + offB[1][ks]);
                ldsm_x4(bl + 0, sb + 28672 + offB[0][ks]);
                ldsm_x4(bl + 4, sb + 28672 + offB[1][ks]);
#pragma unroll
                for (int ni = 0; ni < 4; ni++) {
                    const uint32_t* ph = &bh[(ni >> 1) * 4 + (ni & 1) * 2];
                    const uint32_t* pl = &bl[(ni >> 1) * 4 + (ni & 1) * 2];
#pragma unroll
                    for (int mi = 0; mi < 2; mi++) {
                        mma16816(accu[mi][ni], ahi[mi], ph);
                        mma16816(accu[mi][ni], ahi[mi], pl);
                        mma16816(accu[mi][ni], alo[mi], ph);
                    }
                }
            }
        }
        cb = (cb == 2) ? 0 : cb + 1;
        lb = (lb == 2) ? 0 : lb + 1;
    }

    // epilogue: h = silu(g)*u, split to bf16 hi/lo
    const int gRow = lane >> 2;
    const int cp2 = (lane & 3) * 2;
#pragma unroll
    for (int mi = 0; mi < 2; mi++) {
#pragma unroll
        for (int ni = 0; ni < 4; ni++) {
            int col = n0 + wc * 32 + ni * 8 + cp2;
            int r0 = wr * 32 + mi * 16 + gRow;
#pragma unroll
            for (int half = 0; half < 2; half++) {
                int slot = row0 + r0 + half * 8;
                if (slot < end) {
                    float g0 = accg[mi][ni][half * 2 + 0];
                    float g1 = accg[mi][ni][half * 2 + 1];
                    float u0 = accu[mi][ni][half * 2 + 0];
                    float u1 = accu[mi][ni][half * 2 + 1];
                    float h0 = silu_f(g0) * u0;
                    float h1 = silu_f(g1) * u1;
                    __nv_bfloat162 vh, vl;
                    vh.x = __float2bfloat16(h0);
                    vl.x = __float2bfloat16(h0 - __bfloat162float(vh.x));
                    vh.y = __float2bfloat16(h1);
                    vl.y = __float2bfloat16(h1 - __bfloat162float(vh.y));
                    *reinterpret_cast<__nv_bfloat162*>(g_hhi + (size_t)slot * PI + col) = vh;
                    *reinterpret_cast<__nv_bfloat162*>(g_hlo + (size_t)slot * PI + col) = vl;
                }
            }
        }
    }
}

// ============================================================================
// Down kernel: 128 slots x 128 H-cols, BK=32 over I. 3-stage pipeline.
// Epilogue now writes UNWEIGHTED per-slot y (plain float2 stores, no atomics).
// ============================================================================
#define D_STAGE 32768
#define D_SMEM  (3 * D_STAGE + 512)

__device__ __forceinline__ void d_load_stage(uint32_t sb, int row0, size_t eoff,
                                             int n0, int k0, int tid) {
#pragma unroll
    for (int it = 0; it < 4; it++) {
        int idx = tid + it * 256;
        int t = idx >> 9;
        int r = (idx >> 2) & 127;
        int c = idx & 3;
        int slot = row0 + r;
        if (slot >= PNK) slot = PNK - 1;
        const __nv_bfloat16* src =
            (t ? g_hlo : g_hhi) + (size_t)slot * PI + k0 + c * 8;
        cpa16(sb + t * 8192 + SWO(r, c), src);
    }
#pragma unroll
    for (int it = 0; it < 4; it++) {
        int idx = tid + it * 256;
        int t = idx >> 9;
        int r = (idx >> 2) & 127;
        int c = idx & 3;
        const __nv_bfloat16* src =
            (t ? g_wdlo : g_wdhi) + eoff + (size_t)(n0 + r) * PI + k0 + c * 8;
        cpa16(sb + 16384 + t * 8192 + SWO(r, c), src);
    }
}

__global__ __launch_bounds__(256, 2) void k_down() {
    extern __shared__ __align__(128) char smem[];
    const int e = blockIdx.z;
    const int beg = g_offsets[e];
    const int end = g_offsets[e + 1];
    const int row0 = beg + blockIdx.x * 128;
    if (row0 >= end) return;
    const int n0 = blockIdx.y * 128;

    const int tid = threadIdx.x;
    const int wid = tid >> 5;
    const int lane = tid & 31;
    const int wr = wid >> 1;   // rows wr*32..+31
    const int wc = wid & 1;    // cols wc*64..+63

    const size_t eoff = (size_t)e * PH * PI;

    float acc[2][8][4];
#pragma unroll
    for (int mi = 0; mi < 2; mi++)
#pragma unroll
        for (int ni = 0; ni < 8; ni++)
#pragma unroll
            for (int q = 0; q < 4; q++) acc[mi][ni][q] = 0.0f;

    const uint32_t sb0 = smem_u32(smem);

    uint32_t offA[2][2], offB[4][2];
    {
        const int rA = wr * 32 + (lane & 15);
        const int cA = lane >> 4;
#pragma unroll
        for (int mi = 0; mi < 2; mi++)
#pragma unroll
            for (int ks = 0; ks < 2; ks++)
                offA[mi][ks] = SWO(rA + mi * 16, cA + 2 * ks);
        const int rB = (lane & 7) + 8 * ((lane >> 4) & 1);
        const int cB = (lane >> 3) & 1;
#pragma unroll
        for (int h = 0; h < 4; h++)
#pragma unroll
            for (int ks = 0; ks < 2; ks++)
                offB[h][ks] = SWO(wc * 64 + 16 * h + rB, cB + 2 * ks);
    }

    d_load_stage(sb0, row0, eoff, n0, 0, tid);
    CP_COMMIT();
    d_load_stage(sb0 + D_STAGE, row0, eoff, n0, 32, tid);
    CP_COMMIT();

    const int NC = PI / 32;  // 44
    int cb = 0, lb = 2;
    for (int c = 0; c < NC; c++) {
        CP_WAIT1();
        __syncthreads();
        if (c + 2 < NC)
            d_load_stage(sb0 + lb * D_STAGE, row0, eoff, n0, (c + 2) * 32, tid);
        CP_COMMIT();

        const uint32_t sb = sb0 + cb * D_STAGE;
#pragma unroll
        for (int ks = 0; ks < 2; ks++) {
            uint32_t ahi[2][4], alo[2][4];
            ldsm_x4(ahi[0], sb + offA[0][ks]);
            ldsm_x4(ahi[1], sb + offA[1][ks]);
            ldsm_x4(alo[0], sb + 8192 + offA[0][ks]);
            ldsm_x4(alo[1], sb + 8192 + offA[1][ks]);
#pragma unroll
            for (int h = 0; h < 4; h++) {
                uint32_t bh[4], bl[4];
                ldsm_x4(bh, sb + 16384 + offB[h][ks]);
                ldsm_x4(bl, sb + 24576 + offB[h][ks]);
#pragma unroll
                for (int sub = 0; sub < 2; sub++) {
                    int ni = h * 2 + sub;
                    const uint32_t* ph = &bh[sub * 2];
                    const uint32_t* pl = &bl[sub * 2];
#pragma unroll
                    for (int mi = 0; mi < 2; mi++) {
                        mma16816(acc[mi][ni], ahi[mi], ph);
                        mma16816(acc[mi][ni], ahi[mi], pl);
                        mma16816(acc[mi][ni], alo[mi], ph);
                    }
                }
            }
        }
        cb = (cb == 2) ? 0 : cb + 1;
        lb = (lb == 2) ? 0 : lb + 1;
    }

    // epilogue: y[slot][col] = acc (plain stores; weights applied in combine)
    const int gRow = lane >> 2;
    const int cp2 = (lane & 3) * 2;
#pragma unroll
    for (int mi = 0; mi < 2; mi++) {
#pragma unroll
        for (int ni = 0; ni < 8; ni++) {
            int col = n0 + wc * 64 + ni * 8 + cp2;
            int r0 = wr * 32 + mi * 16 + gRow;
#pragma unroll
            for (int half = 0; half < 2; half++) {
                int lr = r0 + half * 8;
                int slot = row0 + lr;
                if (slot < end) {
                    float2 v;
                    v.x = acc[mi][ni][half * 2 + 0];
                    v.y = acc[mi][ni][half * 2 + 1];
                    *reinterpret_cast<float2*>(g_y + (size_t)slot * PH + col) = v;
                }
            }
        }
    }
}

// ---------------- combine: out[n] = w0*y[slot0] + w1*y[slot1] ----------------
__global__ void k_combine(const float* __restrict__ tw, float* __restrict__ out) {
    int idx = blockIdx.x * blockDim.x + threadIdx.x;  // over PN * (PH/4)
    if (idx >= PN * (PH / 4)) return;
    int n = idx / (PH / 4);
    int hq = idx % (PH / 4);
    int s0 = g_pair_slot[n * 2 + 0];
    int s1 = g_pair_slot[n * 2 + 1];
    float w0 = tw[n * 2 + 0];
    float w1 = tw[n * 2 + 1];
    float4 a = *reinterpret_cast<const float4*>(g_y + (size_t)s0 * PH + hq * 4);
    float4 b = *reinterpret_cast<const float4*>(g_y + (size_t)s1 * PH + hq * 4);
    float4 o;
    o.x = w0 * a.x + w1 * b.x;
    o.y = w0 * a.y + w1 * b.y;
    o.z = w0 * a.z + w1 * b.z;
    o.w = w0 * a.w + w1 * b.w;
    *reinterpret_cast<float4*>(out + (size_t)n * PH + hq * 4) = o;
}

// ---------------- launch ----------------
extern "C" void kernel_launch(void* const* d_in, const int* in_sizes, int n_in,
                              void* d_out, int out_size) {
    const float* x = (const float*)d_in[0];          // [N, H]
    const int* topk_ids = (const int*)d_in[1];       // [N, K]
    const float* topk_w = (const float*)d_in[2];     // [N, K]
    const float* Wg = (const float*)d_in[3];         // [E, I, H]
    const float* Wu = (const float*)d_in[4];         // [E, I, H]
    const float* Wd = (const float*)d_in[5];         // [E, H, I]
    float* out = (float*)d_out;                      // [N, H]

    static bool attr_done = false;
    if (!attr_done) {
        cudaFuncSetAttribute(k_gu, cudaFuncAttributeMaxDynamicSharedMemorySize, GU_SMEM);
        cudaFuncSetAttribute(k_down, cudaFuncAttributeMaxDynamicSharedMemorySize, D_SMEM);
        attr_done = true;
    }

    // launch index:           0        1          2           3           4
    k_route<<<1, 256>>>(topk_ids);
    k_split_x<<<4096, 256>>>(x);
    k_split_wg<<<8192, 256>>>(Wg);
    k_split_wu<<<8192, 256>>>(Wu);
    k_split_wd<<<8192, 256>>>(Wd);
    // launch index 5 == k_gu (ncu -s 5 -c 1 captures this)
    {
        dim3 grid(PN / 128, PI / 64, PE);    // 32 x 22 x 8
        k_gu<<<grid, 256, GU_SMEM>>>();
    }
    // launch index 6
    {
        dim3 grid(PN / 128, PH / 128, PE);   // 32 x 16 x 8
        k_down<<<grid, 256, D_SMEM>>>();
    }
    // launch index 7
    k_combine<<<(PN * (PH / 4) + 255) / 256, 256>>>(topk_w, out);
}

// round 12
// speedup vs baseline: 2.8413x; 1.0044x over previous
#include <cuda_runtime.h>
#include <cuda_bf16.h>
#include <cstdint>

// Problem constants
#define PN 4096
#define PTOPK 2
#define PE 8
#define PH 2048
#define PI 1408
#define PNK (PN * PTOPK)   // 8192

// ---------------- device scratch ----------------
__device__ int g_offsets[PE + 1];
__device__ int g_pair_token[PNK];
__device__ int g_pair_slot[PNK];

__device__ __align__(16) __nv_bfloat16 g_xhi[(size_t)PN * PH];
__device__ __align__(16) __nv_bfloat16 g_xlo[(size_t)PN * PH];
__device__ __align__(16) __nv_bfloat16 g_wghi[(size_t)PE * PI * PH];
__device__ __align__(16) __nv_bfloat16 g_wglo[(size_t)PE * PI * PH];
__device__ __align__(16) __nv_bfloat16 g_wuhi[(size_t)PE * PI * PH];
__device__ __align__(16) __nv_bfloat16 g_wulo[(size_t)PE * PI * PH];
__device__ __align__(16) __nv_bfloat16 g_wdhi[(size_t)PE * PH * PI];
__device__ __align__(16) __nv_bfloat16 g_wdlo[(size_t)PE * PH * PI];
__device__ __align__(16) __nv_bfloat16 g_hhi[(size_t)PNK * PI];
__device__ __align__(16) __nv_bfloat16 g_hlo[(size_t)PNK * PI];
__device__ __align__(16) float g_y[(size_t)PNK * PH];

// ---------------- helpers ----------------
__device__ __forceinline__ uint32_t smem_u32(const void* p) {
    return (uint32_t)__cvta_generic_to_shared(p);
}

__device__ __forceinline__ void cpa16(uint32_t dst, const void* src) {
    asm volatile("cp.async.cg.shared.global [%0], [%1], 16;" :: "r"(dst), "l"(src) : "memory");
}
#define CP_COMMIT() asm volatile("cp.async.commit_group;" ::: "memory")
#define CP_WAIT1()  asm volatile("cp.async.wait_group 1;" ::: "memory")

__device__ __forceinline__ void ldsm_x4(uint32_t* r, uint32_t addr) {
    asm volatile("ldmatrix.sync.aligned.m8n8.x4.shared.b16 {%0,%1,%2,%3}, [%4];"
                 : "=r"(r[0]), "=r"(r[1]), "=r"(r[2]), "=r"(r[3]) : "r"(addr) : "memory");
}
__device__ __forceinline__ void mma16816(float* c, const uint32_t* a, const uint32_t* b) {
    asm volatile("mma.sync.aligned.m16n8k16.row.col.f32.bf16.bf16.f32 "
                 "{%0,%1,%2,%3}, {%4,%5,%6,%7}, {%8,%9}, {%0,%1,%2,%3};"
                 : "+f"(c[0]), "+f"(c[1]), "+f"(c[2]), "+f"(c[3])
                 : "r"(a[0]), "r"(a[1]), "r"(a[2]), "r"(a[3]), "r"(b[0]), "r"(b[1])
                 : "memory");
}

__device__ __forceinline__ float silu_f(float g) {
    return g / (1.0f + __expf(-g));
}

// 64B-pitch XOR swizzle: row r, 16B-chunk c (0..3). Conflict-free for
// cp.async stores and all ldmatrix phases.
#define SWO(r, c) ((uint32_t)((r) * 64 + ((((c) ^ (((r) >> 1) & 3))) * 16)))

// ---------------- routing: ONE single-CTA kernel ----------------
__global__ void k_route(const int* __restrict__ ids) {
    __shared__ int cnt[PE];
    __shared__ int off[PE + 1];
    __shared__ int cur[PE];
    const int tid = threadIdx.x;
    if (tid < PE) { cnt[tid] = 0; cur[tid] = 0; }
    __syncthreads();
    for (int i = tid; i < PNK; i += 256) atomicAdd(&cnt[ids[i]], 1);
    __syncthreads();
    if (tid == 0) {
        int s = 0;
        for (int e = 0; e < PE; e++) { off[e] = s; g_offsets[e] = s; s += cnt[e]; }
        off[PE] = s;
        g_offsets[PE] = s;
    }
    __syncthreads();
    for (int i = tid; i < PNK; i += 256) {
        int e = ids[i];
        int pos = off[e] + atomicAdd(&cur[e], 1);
        g_pair_token[pos] = i / PTOPK;
        g_pair_slot[i] = pos;
    }
}

// ---------------- fp32 -> bf16 hi/lo split ----------------
// Destination globals referenced from DEVICE code only (host-shadow pitfall).
__device__ __forceinline__ void split_elem(const float* __restrict__ src,
                                           __nv_bfloat16* __restrict__ hi,
                                           __nv_bfloat16* __restrict__ lo, int i) {
    float4 v = reinterpret_cast<const float4*>(src)[i];
    __nv_bfloat162 h0, h1, l0, l1;
    h0.x = __float2bfloat16(v.x); l0.x = __float2bfloat16(v.x - __bfloat162float(h0.x));
    h0.y = __float2bfloat16(v.y); l0.y = __float2bfloat16(v.y - __bfloat162float(h0.y));
    h1.x = __float2bfloat16(v.z); l1.x = __float2bfloat16(v.z - __bfloat162float(h1.x));
    h1.y = __float2bfloat16(v.w); l1.y = __float2bfloat16(v.w - __bfloat162float(h1.y));
    reinterpret_cast<__nv_bfloat162*>(hi)[i * 2 + 0] = h0;
    reinterpret_cast<__nv_bfloat162*>(hi)[i * 2 + 1] = h1;
    reinterpret_cast<__nv_bfloat162*>(lo)[i * 2 + 0] = l0;
    reinterpret_cast<__nv_bfloat162*>(lo)[i * 2 + 1] = l1;
}

__global__ void k_split_x(const float* __restrict__ src) {
    const int n4 = PN * PH / 4;
    int i = blockIdx.x * blockDim.x + threadIdx.x;
    int stride = gridDim.x * blockDim.x;
    for (; i < n4; i += stride) split_elem(src, g_xhi, g_xlo, i);
}
// merged gate+up weight split: same index in both tensors per thread
__global__ void k_split_wgu(const float* __restrict__ wg, const float* __restrict__ wu) {
    const int n4 = PE * PI * PH / 4;
    int i = blockIdx.x * blockDim.x + threadIdx.x;
    int stride = gridDim.x * blockDim.x;
    for (; i < n4; i += stride) {
        split_elem(wg, g_wghi, g_wglo, i);
        split_elem(wu, g_wuhi, g_wulo, i);
    }
}
__global__ void k_split_wd(const float* __restrict__ src) {
    const int n4 = PE * PH * PI / 4;
    int i = blockIdx.x * blockDim.x + threadIdx.x;
    int stride = gridDim.x * blockDim.x;
    for (; i < n4; i += stride) split_elem(src, g_wdhi, g_wdlo, i);
}

// ============================================================================
// GU kernel: split-bf16 mma.sync, 128 slots x (64 gate + 64 up), BK=32.
// 3-stage cp.async pipeline, 64B-pitch XOR swizzle, one barrier per chunk.
// ============================================================================
#define GU_STAGE 32768
#define GU_SMEM  (3 * GU_STAGE + 512)

__device__ __forceinline__ void gu_load_stage(uint32_t sb, const int* s_tok, size_t eoff,
                                              int n0, int k0, int tid) {
#pragma unroll
    for (int it = 0; it < 4; it++) {
        int idx = tid + it * 256;
        int t = idx >> 9;
        int r = (idx >> 2) & 127;
        int c = idx & 3;
        const __nv_bfloat16* src =
            (t ? g_xlo : g_xhi) + (size_t)s_tok[r] * PH + k0 + c * 8;
        cpa16(sb + t * 8192 + SWO(r, c), src);
    }
#pragma unroll
    for (int it = 0; it < 4; it++) {
        int idx = tid + it * 256;
        int t = idx >> 8;          // 0..3
        int r = (idx >> 2) & 63;
        int c = idx & 3;
        const __nv_bfloat16* base;
        if (t == 0) base = g_wghi;
        else if (t == 1) base = g_wglo;
        else if (t == 2) base = g_wuhi;
        else base = g_wulo;
        const __nv_bfloat16* src = base + eoff + (size_t)(n0 + r) * PH + k0 + c * 8;
        cpa16(sb + 16384 + t * 4096 + SWO(r, c), src);
    }
}

__global__ __launch_bounds__(256, 2) void k_gu() {
    extern __shared__ __align__(128) char smem[];
    const int e = blockIdx.z;
    const int beg = g_offsets[e];
    const int end = g_offsets[e + 1];
    const int row0 = beg + blockIdx.x * 128;
    if (row0 >= end) return;
    const int n0 = blockIdx.y * 64;

    const int tid = threadIdx.x;
    const int wid = tid >> 5;
    const int lane = tid & 31;
    const int wr = wid >> 1;   // rows wr*32..+31
    const int wc = wid & 1;    // cols wc*32..+31

    int* s_tok = reinterpret_cast<int*>(smem + 3 * GU_STAGE);
    if (tid < 128) {
        int slot = row0 + tid;
        if (slot >= PNK) slot = PNK - 1;
        s_tok[tid] = g_pair_token[slot];
    }
    __syncthreads();

    const size_t eoff = (size_t)e * PI * PH;

    float accg[2][4][4];
    float accu[2][4][4];
#pragma unroll
    for (int mi = 0; mi < 2; mi++)
#pragma unroll
        for (int ni = 0; ni < 4; ni++)
#pragma unroll
            for (int q = 0; q < 4; q++) { accg[mi][ni][q] = 0.0f; accu[mi][ni][q] = 0.0f; }

    const uint32_t sb0 = smem_u32(smem);

    uint32_t offA[2][2], offB[2][2];
    {
        const int rA = wr * 32 + (lane & 15);
        const int cA = lane >> 4;
#pragma unroll
        for (int mi = 0; mi < 2; mi++)
#pragma unroll
            for (int ks = 0; ks < 2; ks++)
                offA[mi][ks] = SWO(rA + mi * 16, cA + 2 * ks);
        const int rB = (lane & 7) + 8 * ((lane >> 4) & 1);
        const int cB = (lane >> 3) & 1;
#pragma unroll
        for (int h = 0; h < 2; h++)
#pragma unroll
            for (int ks = 0; ks < 2; ks++)
                offB[h][ks] = SWO(wc * 32 + 16 * h + rB, cB + 2 * ks);
    }

    gu_load_stage(sb0, s_tok, eoff, n0, 0, tid);
    CP_COMMIT();
    gu_load_stage(sb0 + GU_STAGE, s_tok, eoff, n0, 32, tid);
    CP_COMMIT();

    const int NC = PH / 32;  // 64
    int cb = 0, lb = 2;
    for (int c = 0; c < NC; c++) {
        CP_WAIT1();
        __syncthreads();
        if (c + 2 < NC)
            gu_load_stage(sb0 + lb * GU_STAGE, s_tok, eoff, n0, (c + 2) * 32, tid);
        CP_COMMIT();

        const uint32_t sb = sb0 + cb * GU_STAGE;
#pragma unroll
        for (int ks = 0; ks < 2; ks++) {
            uint32_t ahi[2][4], alo[2][4];
            ldsm_x4(ahi[0], sb + offA[0][ks]);
            ldsm_x4(ahi[1], sb + offA[1][ks]);
            ldsm_x4(alo[0], sb + 8192 + offA[0][ks]);
            ldsm_x4(alo[1], sb + 8192 + offA[1][ks]);
            {   // gate
                uint32_t bh[8], bl[8];
                ldsm_x4(bh + 0, sb + 16384 + offB[0][ks]);
                ldsm_x4(bh + 4, sb + 16384 + offB[1][ks]);
                ldsm_x4(bl + 0, sb + 20480 + offB[0][ks]);
                ldsm_x4(bl + 4, sb + 20480 + offB[1][ks]);
#pragma unroll
                for (int ni = 0; ni < 4; ni++) {
                    const uint32_t* ph = &bh[(ni >> 1) * 4 + (ni & 1) * 2];
                    const uint32_t* pl = &bl[(ni >> 1) * 4 + (ni & 1) * 2];
#pragma unroll
                    for (int mi = 0; mi < 2; mi++) {
                        mma16816(accg[mi][ni], ahi[mi], ph);
                        mma16816(accg[mi][ni], ahi[mi], pl);
                        mma16816(accg[mi][ni], alo[mi], ph);
                    }
                }
            }
            {   // up
                uint32_t bh[8], bl[8];
                ldsm_x4(bh + 0, sb + 24576 + offB[0][ks]);
                ldsm_x4(bh + 4, sb + 24576 + offB[1][ks]);
                ldsm_x4(bl + 0, sb + 28672 + offB[0][ks]);
                ldsm_x4(bl + 4, sb + 28672 + offB[1][ks]);
#pragma unroll
                for (int ni = 0; ni < 4; ni++) {
                    const uint32_t* ph = &bh[(ni >> 1) * 4 + (ni & 1) * 2];
                    const uint32_t* pl = &bl[(ni >> 1) * 4 + (ni & 1) * 2];
#pragma unroll
                    for (int mi = 0; mi < 2; mi++) {
                        mma16816(accu[mi][ni], ahi[mi], ph);
                        mma16816(accu[mi][ni], ahi[mi], pl);
                        mma16816(accu[mi][ni], alo[mi], ph);
                    }
                }
            }
        }
        cb = (cb == 2) ? 0 : cb + 1;
        lb = (lb == 2) ? 0 : lb + 1;
    }

    // epilogue: h = silu(g)*u, split to bf16 hi/lo
    const int gRow = lane >> 2;
    const int cp2 = (lane & 3) * 2;
#pragma unroll
    for (int mi = 0; mi < 2; mi++) {
#pragma unroll
        for (int ni = 0; ni < 4; ni++) {
            int col = n0 + wc * 32 + ni * 8 + cp2;
            int r0 = wr * 32 + mi * 16 + gRow;
#pragma unroll
            for (int half = 0; half < 2; half++) {
                int slot = row0 + r0 + half * 8;
                if (slot < end) {
                    float g0 = accg[mi][ni][half * 2 + 0];
                    float g1 = accg[mi][ni][half * 2 + 1];
                    float u0 = accu[mi][ni][half * 2 + 0];
                    float u1 = accu[mi][ni][half * 2 + 1];
                    float h0 = silu_f(g0) * u0;
                    float h1 = silu_f(g1) * u1;
                    __nv_bfloat162 vh, vl;
                    vh.x = __float2bfloat16(h0);
                    vl.x = __float2bfloat16(h0 - __bfloat162float(vh.x));
                    vh.y = __float2bfloat16(h1);
                    vl.y = __float2bfloat16(h1 - __bfloat162float(vh.y));
                    *reinterpret_cast<__nv_bfloat162*>(g_hhi + (size_t)slot * PI + col) = vh;
                    *reinterpret_cast<__nv_bfloat162*>(g_hlo + (size_t)slot * PI + col) = vl;
                }
            }
        }
    }
}

// ============================================================================
// Down kernel: 128 slots x 128 H-cols, BK=32 over I. 3-stage pipeline.
// Epilogue writes UNWEIGHTED per-slot y (plain float2 stores, no atomics).
// ============================================================================
#define D_STAGE 32768
#define D_SMEM  (3 * D_STAGE + 512)

__device__ __forceinline__ void d_load_stage(uint32_t sb, int row0, size_t eoff,
                                             int n0, int k0, int tid) {
#pragma unroll
    for (int it = 0; it < 4; it++) {
        int idx = tid + it * 256;
        int t = idx >> 9;
        int r = (idx >> 2) & 127;
        int c = idx & 3;
        int slot = row0 + r;
        if (slot >= PNK) slot = PNK - 1;
        const __nv_bfloat16* src =
            (t ? g_hlo : g_hhi) + (size_t)slot * PI + k0 + c * 8;
        cpa16(sb + t * 8192 + SWO(r, c), src);
    }
#pragma unroll
    for (int it = 0; it < 4; it++) {
        int idx = tid + it * 256;
        int t = idx >> 9;
        int r = (idx >> 2) & 127;
        int c = idx & 3;
        const __nv_bfloat16* src =
            (t ? g_wdlo : g_wdhi) + eoff + (size_t)(n0 + r) * PI + k0 + c * 8;
        cpa16(sb + 16384 + t * 8192 + SWO(r, c), src);
    }
}

__global__ __launch_bounds__(256, 2) void k_down() {
    extern __shared__ __align__(128) char smem[];
    const int e = blockIdx.z;
    const int beg = g_offsets[e];
    const int end = g_offsets[e + 1];
    const int row0 = beg + blockIdx.x * 128;
    if (row0 >= end) return;
    const int n0 = blockIdx.y * 128;

    const int tid = threadIdx.x;
    const int wid = tid >> 5;
    const int lane = tid & 31;
    const int wr = wid >> 1;   // rows wr*32..+31
    const int wc = wid & 1;    // cols wc*64..+63

    const size_t eoff = (size_t)e * PH * PI;

    float acc[2][8][4];
#pragma unroll
    for (int mi = 0; mi < 2; mi++)
#pragma unroll
        for (int ni = 0; ni < 8; ni++)
#pragma unroll
            for (int q = 0; q < 4; q++) acc[mi][ni][q] = 0.0f;

    const uint32_t sb0 = smem_u32(smem);

    uint32_t offA[2][2], offB[4][2];
    {
        const int rA = wr * 32 + (lane & 15);
        const int cA = lane >> 4;
#pragma unroll
        for (int mi = 0; mi < 2; mi++)
#pragma unroll
            for (int ks = 0; ks < 2; ks++)
                offA[mi][ks] = SWO(rA + mi * 16, cA + 2 * ks);
        const int rB = (lane & 7) + 8 * ((lane >> 4) & 1);
        const int cB = (lane >> 3) & 1;
#pragma unroll
        for (int h = 0; h < 4; h++)
#pragma unroll
            for (int ks = 0; ks < 2; ks++)
                offB[h][ks] = SWO(wc * 64 + 16 * h + rB, cB + 2 * ks);
    }

    d_load_stage(sb0, row0, eoff, n0, 0, tid);
    CP_COMMIT();
    d_load_stage(sb0 + D_STAGE, row0, eoff, n0, 32, tid);
    CP_COMMIT();

    const int NC = PI / 32;  // 44
    int cb = 0, lb = 2;
    for (int c = 0; c < NC; c++) {
        CP_WAIT1();
        __syncthreads();
        if (c + 2 < NC)
            d_load_stage(sb0 + lb * D_STAGE, row0, eoff, n0, (c + 2) * 32, tid);
        CP_COMMIT();

        const uint32_t sb = sb0 + cb * D_STAGE;
#pragma unroll
        for (int ks = 0; ks < 2; ks++) {
            uint32_t ahi[2][4], alo[2][4];
            ldsm_x4(ahi[0], sb + offA[0][ks]);
            ldsm_x4(ahi[1], sb + offA[1][ks]);
            ldsm_x4(alo[0], sb + 8192 + offA[0][ks]);
            ldsm_x4(alo[1], sb + 8192 + offA[1][ks]);
#pragma unroll
            for (int h = 0; h < 4; h++) {
                uint32_t bh[4], bl[4];
                ldsm_x4(bh, sb + 16384 + offB[h][ks]);
                ldsm_x4(bl, sb + 24576 + offB[h][ks]);
#pragma unroll
                for (int sub = 0; sub < 2; sub++) {
                    int ni = h * 2 + sub;
                    const uint32_t* ph = &bh[sub * 2];
                    const uint32_t* pl = &bl[sub * 2];
#pragma unroll
                    for (int mi = 0; mi < 2; mi++) {
                        mma16816(acc[mi][ni], ahi[mi], ph);
                        mma16816(acc[mi][ni], ahi[mi], pl);
                        mma16816(acc[mi][ni], alo[mi], ph);
                    }
                }
            }
        }
        cb = (cb == 2) ? 0 : cb + 1;
        lb = (lb == 2) ? 0 : lb + 1;
    }

    // epilogue: y[slot][col] = acc (plain stores; weights applied in combine)
    const int gRow = lane >> 2;
    const int cp2 = (lane & 3) * 2;
#pragma unroll
    for (int mi = 0; mi < 2; mi++) {
#pragma unroll
        for (int ni = 0; ni < 8; ni++) {
            int col = n0 + wc * 64 + ni * 8 + cp2;
            int r0 = wr * 32 + mi * 16 + gRow;
#pragma unroll
            for (int half = 0; half < 2; half++) {
                int lr = r0 + half * 8;
                int slot = row0 + lr;
                if (slot < end) {
                    float2 v;
                    v.x = acc[mi][ni][half * 2 + 0];
                    v.y = acc[mi][ni][half * 2 + 1];
                    *reinterpret_cast<float2*>(g_y + (size_t)slot * PH + col) = v;
                }
            }
        }
    }
}

// ---------------- combine: out[n] = w0*y[slot0] + w1*y[slot1] ----------------
__global__ void k_combine(const float* __restrict__ tw, float* __restrict__ out) {
    int idx = blockIdx.x * blockDim.x + threadIdx.x;  // over PN * (PH/4)
    if (idx >= PN * (PH / 4)) return;
    int n = idx / (PH / 4);
    int hq = idx % (PH / 4);
    int s0 = g_pair_slot[n * 2 + 0];
    int s1 = g_pair_slot[n * 2 + 1];
    float w0 = tw[n * 2 + 0];
    float w1 = tw[n * 2 + 1];
    float4 a = *reinterpret_cast<const float4*>(g_y + (size_t)s0 * PH + hq * 4);
    float4 b = *reinterpret_cast<const float4*>(g_y + (size_t)s1 * PH + hq * 4);
    float4 o;
    o.x = w0 * a.x + w1 * b.x;
    o.y = w0 * a.y + w1 * b.y;
    o.z = w0 * a.z + w1 * b.z;
    o.w = w0 * a.w + w1 * b.w;
    *reinterpret_cast<float4*>(out + (size_t)n * PH + hq * 4) = o;
}

// ---------------- launch ----------------
extern "C" void kernel_launch(void* const* d_in, const int* in_sizes, int n_in,
                              void* d_out, int out_size) {
    const float* x = (const float*)d_in[0];          // [N, H]
    const int* topk_ids = (const int*)d_in[1];       // [N, K]
    const float* topk_w = (const float*)d_in[2];     // [N, K]
    const float* Wg = (const float*)d_in[3];         // [E, I, H]
    const float* Wu = (const float*)d_in[4];         // [E, I, H]
    const float* Wd = (const float*)d_in[5];         // [E, H, I]
    float* out = (float*)d_out;                      // [N, H]

    static bool attr_done = false;
    if (!attr_done) {
        cudaFuncSetAttribute(k_gu, cudaFuncAttributeMaxDynamicSharedMemorySize, GU_SMEM);
        cudaFuncSetAttribute(k_down, cudaFuncAttributeMaxDynamicSharedMemorySize, D_SMEM);
        attr_done = true;
    }

    // launch index 0..2
    k_route<<<1, 256>>>(topk_ids);
    k_split_x<<<4096, 256>>>(x);
    k_split_wgu<<<8192, 256>>>(Wg, Wu);
    // launch index 3 == k_gu  (observed: ncu capture lands on the 4th launch)
    {
        dim3 grid(PN / 128, PI / 64, PE);    // 32 x 22 x 8
        k_gu<<<grid, 256, GU_SMEM>>>();
    }
    // launch index 4: wd split (needed only by k_down)
    k_split_wd<<<8192, 256>>>(Wd);
    // launch index 5
    {
        dim3 grid(PN / 128, PH / 128, PE);   // 32 x 16 x 8
        k_down<<<grid, 256, D_SMEM>>>();
    }
    // launch index 6
    k_combine<<<(PN * (PH / 4) + 255) / 256, 256>>>(topk_w, out);
}

// round 13
// speedup vs baseline: 3.9982x; 1.4072x over previous
#include <cuda_runtime.h>
#include <cuda_fp16.h>
#include <cstdint>

// Problem constants
#define PN 4096
#define PTOPK 2
#define PE 8
#define PH 2048
#define PI 1408
#define PNK (PN * PTOPK)   // 8192

// ---------------- device scratch ----------------
__device__ int g_offsets[PE + 1];
__device__ int g_pair_token[PNK];
__device__ int g_pair_slot[PNK];

__device__ __align__(16) __half g_xhi[(size_t)PN * PH];
__device__ __align__(16) __half g_xlo[(size_t)PN * PH];
__device__ __align__(16) __half g_wghi[(size_t)PE * PI * PH];
__device__ __align__(16) __half g_wuhi[(size_t)PE * PI * PH];
__device__ __align__(16) __half g_wdhi[(size_t)PE * PH * PI];
__device__ __align__(16) __half g_hhi[(size_t)PNK * PI];
__device__ __align__(16) __half g_hlo[(size_t)PNK * PI];
__device__ __align__(16) float g_y[(size_t)PNK * PH];

// ---------------- helpers ----------------
__device__ __forceinline__ uint32_t smem_u32(const void* p) {
    return (uint32_t)__cvta_generic_to_shared(p);
}

__device__ __forceinline__ void cpa16(uint32_t dst, const void* src) {
    asm volatile("cp.async.cg.shared.global [%0], [%1], 16;" :: "r"(dst), "l"(src) : "memory");
}
#define CP_COMMIT() asm volatile("cp.async.commit_group;" ::: "memory")
#define CP_WAIT1()  asm volatile("cp.async.wait_group 1;" ::: "memory")

__device__ __forceinline__ void ldsm_x4(uint32_t* r, uint32_t addr) {
    asm volatile("ldmatrix.sync.aligned.m8n8.x4.shared.b16 {%0,%1,%2,%3}, [%4];"
                 : "=r"(r[0]), "=r"(r[1]), "=r"(r[2]), "=r"(r[3]) : "r"(addr) : "memory");
}
// fp16 mma, fp32 accumulate
__device__ __forceinline__ void mma16816(float* c, const uint32_t* a, const uint32_t* b) {
    asm volatile("mma.sync.aligned.m16n8k16.row.col.f32.f16.f16.f32 "
                 "{%0,%1,%2,%3}, {%4,%5,%6,%7}, {%8,%9}, {%0,%1,%2,%3};"
                 : "+f"(c[0]), "+f"(c[1]), "+f"(c[2]), "+f"(c[3])
                 : "r"(a[0]), "r"(a[1]), "r"(a[2]), "r"(a[3]), "r"(b[0]), "r"(b[1])
                 : "memory");
}

__device__ __forceinline__ float silu_f(float g) {
    return g / (1.0f + __expf(-g));
}

// 64B-pitch XOR swizzle: row r, 16B-chunk c (0..3). Conflict-free for
// cp.async stores and all ldmatrix phases.
#define SWO(r, c) ((uint32_t)((r) * 64 + ((((c) ^ (((r) >> 1) & 3))) * 16)))

// ---------------- routing: ONE single-CTA kernel ----------------
__global__ void k_route(const int* __restrict__ ids) {
    __shared__ int cnt[PE];
    __shared__ int off[PE + 1];
    __shared__ int cur[PE];
    const int tid = threadIdx.x;
    if (tid < PE) { cnt[tid] = 0; cur[tid] = 0; }
    __syncthreads();
    for (int i = tid; i < PNK; i += 256) atomicAdd(&cnt[ids[i]], 1);
    __syncthreads();
    if (tid == 0) {
        int s = 0;
        for (int e = 0; e < PE; e++) { off[e] = s; g_offsets[e] = s; s += cnt[e]; }
        off[PE] = s;
        g_offsets[PE] = s;
    }
    __syncthreads();
    for (int i = tid; i < PNK; i += 256) {
        int e = ids[i];
        int pos = off[e] + atomicAdd(&cur[e], 1);
        g_pair_token[pos] = i / PTOPK;
        g_pair_slot[i] = pos;
    }
}

// ---------------- fp32 -> fp16 conversions ----------------
// Destination globals referenced from DEVICE code only (host-shadow pitfall).

// full hi/lo split (A-side tensors: x)
__global__ void k_split_x(const float* __restrict__ src) {
    const int n4 = PN * PH / 4;
    int i = blockIdx.x * blockDim.x + threadIdx.x;
    int stride = gridDim.x * blockDim.x;
    for (; i < n4; i += stride) {
        float4 v = reinterpret_cast<const float4*>(src)[i];
        __half2 h0, h1, l0, l1;
        h0.x = __float2half_rn(v.x); l0.x = __float2half_rn(v.x - __half2float(h0.x));
        h0.y = __float2half_rn(v.y); l0.y = __float2half_rn(v.y - __half2float(h0.y));
        h1.x = __float2half_rn(v.z); l1.x = __float2half_rn(v.z - __half2float(h1.x));
        h1.y = __float2half_rn(v.w); l1.y = __float2half_rn(v.w - __half2float(h1.y));
        reinterpret_cast<__half2*>(g_xhi)[i * 2 + 0] = h0;
        reinterpret_cast<__half2*>(g_xhi)[i * 2 + 1] = h1;
        reinterpret_cast<__half2*>(g_xlo)[i * 2 + 0] = l0;
        reinterpret_cast<__half2*>(g_xlo)[i * 2 + 1] = l1;
    }
}

// weight rounding: hi only (B-side)
__device__ __forceinline__ void round_elem(const float* __restrict__ src,
                                           __half* __restrict__ hi, int i) {
    float4 v = reinterpret_cast<const float4*>(src)[i];
    __half2 h0, h1;
    h0.x = __float2half_rn(v.x);
    h0.y = __float2half_rn(v.y);
    h1.x = __float2half_rn(v.z);
    h1.y = __float2half_rn(v.w);
    reinterpret_cast<__half2*>(hi)[i * 2 + 0] = h0;
    reinterpret_cast<__half2*>(hi)[i * 2 + 1] = h1;
}

__global__ void k_split_wgu(const float* __restrict__ wg, const float* __restrict__ wu) {
    const int n4 = PE * PI * PH / 4;
    int i = blockIdx.x * blockDim.x + threadIdx.x;
    int stride = gridDim.x * blockDim.x;
    for (; i < n4; i += stride) {
        round_elem(wg, g_wghi, i);
        round_elem(wu, g_wuhi, i);
    }
}
__global__ void k_split_wd(const float* __restrict__ src) {
    const int n4 = PE * PH * PI / 4;
    int i = blockIdx.x * blockDim.x + threadIdx.x;
    int stride = gridDim.x * blockDim.x;
    for (; i < n4; i += stride) round_elem(src, g_wdhi, i);
}

// ============================================================================
// GU kernel: 2-term fp16 mma.sync, 128 slots x (64 gate + 64 up), BK=32.
// 3-stage cp.async pipeline, 64B-pitch XOR swizzle, one barrier per chunk.
// Stage (24576 B): A_hi @0 (8K), A_lo @8192 (8K), Bg @16384 (4K), Bu @20480 (4K).
// ============================================================================
#define GU_STAGE 24576
#define GU_SMEM  (3 * GU_STAGE + 512)

__device__ __forceinline__ void gu_load_stage(uint32_t sb, const int* s_tok, size_t eoff,
                                              int n0, int k0, int tid) {
#pragma unroll
    for (int it = 0; it < 4; it++) {
        int idx = tid + it * 256;          // 0..1023 : A hi/lo
        int t = idx >> 9;
        int r = (idx >> 2) & 127;
        int c = idx & 3;
        const __half* src = (t ? g_xlo : g_xhi) + (size_t)s_tok[r] * PH + k0 + c * 8;
        cpa16(sb + t * 8192 + SWO(r, c), src);
    }
#pragma unroll
    for (int it = 0; it < 2; it++) {
        int idx = tid + it * 256;          // 0..511 : Bg, Bu
        int t = idx >> 8;                  // 0..1
        int r = (idx >> 2) & 63;
        int c = idx & 3;
        const __half* base = t ? g_wuhi : g_wghi;
        const __half* src = base + eoff + (size_t)(n0 + r) * PH + k0 + c * 8;
        cpa16(sb + 16384 + t * 4096 + SWO(r, c), src);
    }
}

__global__ __launch_bounds__(256, 2) void k_gu() {
    extern __shared__ __align__(128) char smem[];
    const int e = blockIdx.z;
    const int beg = g_offsets[e];
    const int end = g_offsets[e + 1];
    const int row0 = beg + blockIdx.x * 128;
    if (row0 >= end) return;
    const int n0 = blockIdx.y * 64;

    const int tid = threadIdx.x;
    const int wid = tid >> 5;
    const int lane = tid & 31;
    const int wr = wid >> 1;   // rows wr*32..+31
    const int wc = wid & 1;    // cols wc*32..+31

    int* s_tok = reinterpret_cast<int*>(smem + 3 * GU_STAGE);
    if (tid < 128) {
        int slot = row0 + tid;
        if (slot >= PNK) slot = PNK - 1;
        s_tok[tid] = g_pair_token[slot];
    }
    __syncthreads();

    const size_t eoff = (size_t)e * PI * PH;

    float accg[2][4][4];
    float accu[2][4][4];
#pragma unroll
    for (int mi = 0; mi < 2; mi++)
#pragma unroll
        for (int ni = 0; ni < 4; ni++)
#pragma unroll
            for (int q = 0; q < 4; q++) { accg[mi][ni][q] = 0.0f; accu[mi][ni][q] = 0.0f; }

    const uint32_t sb0 = smem_u32(smem);

    uint32_t offA[2][2], offB[2][2];
    {
        const int rA = wr * 32 + (lane & 15);
        const int cA = lane >> 4;
#pragma unroll
        for (int mi = 0; mi < 2; mi++)
#pragma unroll
            for (int ks = 0; ks < 2; ks++)
                offA[mi][ks] = SWO(rA + mi * 16, cA + 2 * ks);
        const int rB = (lane & 7) + 8 * ((lane >> 4) & 1);
        const int cB = (lane >> 3) & 1;
#pragma unroll
        for (int h = 0; h < 2; h++)
#pragma unroll
            for (int ks = 0; ks < 2; ks++)
                offB[h][ks] = SWO(wc * 32 + 16 * h + rB, cB + 2 * ks);
    }

    gu_load_stage(sb0, s_tok, eoff, n0, 0, tid);
    CP_COMMIT();
    gu_load_stage(sb0 + GU_STAGE, s_tok, eoff, n0, 32, tid);
    CP_COMMIT();

    const int NC = PH / 32;  // 64
    int cb = 0, lb = 2;
    for (int c = 0; c < NC; c++) {
        CP_WAIT1();
        __syncthreads();
        if (c + 2 < NC)
            gu_load_stage(sb0 + lb * GU_STAGE, s_tok, eoff, n0, (c + 2) * 32, tid);
        CP_COMMIT();

        const uint32_t sb = sb0 + cb * GU_STAGE;
#pragma unroll
        for (int ks = 0; ks < 2; ks++) {
            uint32_t ahi[2][4], alo[2][4];
            ldsm_x4(ahi[0], sb + offA[0][ks]);
            ldsm_x4(ahi[1], sb + offA[1][ks]);
            ldsm_x4(alo[0], sb + 8192 + offA[0][ks]);
            ldsm_x4(alo[1], sb + 8192 + offA[1][ks]);
            {   // gate
                uint32_t bh[8];
                ldsm_x4(bh + 0, sb + 16384 + offB[0][ks]);
                ldsm_x4(bh + 4, sb + 16384 + offB[1][ks]);
#pragma unroll
                for (int ni = 0; ni < 4; ni++) {
                    const uint32_t* ph = &bh[(ni >> 1) * 4 + (ni & 1) * 2];
#pragma unroll
                    for (int mi = 0; mi < 2; mi++) {
                        mma16816(accg[mi][ni], ahi[mi], ph);
                        mma16816(accg[mi][ni], alo[mi], ph);
                    }
                }
            }
            {   // up
                uint32_t bh[8];
                ldsm_x4(bh + 0, sb + 20480 + offB[0][ks]);
                ldsm_x4(bh + 4, sb + 20480 + offB[1][ks]);
#pragma unroll
                for (int ni = 0; ni < 4; ni++) {
                    const uint32_t* ph = &bh[(ni >> 1) * 4 + (ni & 1) * 2];
#pragma unroll
                    for (int mi = 0; mi < 2; mi++) {
                        mma16816(accu[mi][ni], ahi[mi], ph);
                        mma16816(accu[mi][ni], alo[mi], ph);
                    }
                }
            }
        }
        cb = (cb == 2) ? 0 : cb + 1;
        lb = (lb == 2) ? 0 : lb + 1;
    }

    // epilogue: h = silu(g)*u, split to fp16 hi/lo
    const int gRow = lane >> 2;
    const int cp2 = (lane & 3) * 2;
#pragma unroll
    for (int mi = 0; mi < 2; mi++) {
#pragma unroll
        for (int ni = 0; ni < 4; ni++) {
            int col = n0 + wc * 32 + ni * 8 + cp2;
            int r0 = wr * 32 + mi * 16 + gRow;
#pragma unroll
            for (int half_i = 0; half_i < 2; half_i++) {
                int slot = row0 + r0 + half_i * 8;
                if (slot < end) {
                    float g0 = accg[mi][ni][half_i * 2 + 0];
                    float g1 = accg[mi][ni][half_i * 2 + 1];
                    float u0 = accu[mi][ni][half_i * 2 + 0];
                    float u1 = accu[mi][ni][half_i * 2 + 1];
                    float h0 = silu_f(g0) * u0;
                    float h1 = silu_f(g1) * u1;
                    __half2 vh, vl;
                    vh.x = __float2half_rn(h0);
                    vl.x = __float2half_rn(h0 - __half2float(vh.x));
                    vh.y = __float2half_rn(h1);
                    vl.y = __float2half_rn(h1 - __half2float(vh.y));
                    *reinterpret_cast<__half2*>(g_hhi + (size_t)slot * PI + col) = vh;
                    *reinterpret_cast<__half2*>(g_hlo + (size_t)slot * PI + col) = vl;
                }
            }
        }
    }
}

// ============================================================================
// Down kernel: 2-term fp16, 128 slots x 128 H-cols, BK=32 over I.
// Stage (24576 B): A_hi @0 (8K), A_lo @8192 (8K), B @16384 (8K).
// ============================================================================
#define D_STAGE 24576
#define D_SMEM  (3 * D_STAGE + 512)

__device__ __forceinline__ void d_load_stage(uint32_t sb, int row0, size_t eoff,
                                             int n0, int k0, int tid) {
#pragma unroll
    for (int it = 0; it < 4; it++) {
        int idx = tid + it * 256;          // A hi/lo
        int t = idx >> 9;
        int r = (idx >> 2) & 127;
        int c = idx & 3;
        int slot = row0 + r;
        if (slot >= PNK) slot = PNK - 1;
        const __half* src = (t ? g_hlo : g_hhi) + (size_t)slot * PI + k0 + c * 8;
        cpa16(sb + t * 8192 + SWO(r, c), src);
    }
#pragma unroll
    for (int it = 0; it < 2; it++) {
        int idx = tid + it * 256;          // B (wd hi), 128 rows
        int r = (idx >> 2) & 127;
        int c = idx & 3;
        const __half* src = g_wdhi + eoff + (size_t)(n0 + r) * PI + k0 + c * 8;
        cpa16(sb + 16384 + SWO(r, c), src);
    }
}

__global__ __launch_bounds__(256, 2) void k_down() {
    extern __shared__ __align__(128) char smem[];
    const int e = blockIdx.z;
    const int beg = g_offsets[e];
    const int end = g_offsets[e + 1];
    const int row0 = beg + blockIdx.x * 128;
    if (row0 >= end) return;
    const int n0 = blockIdx.y * 128;

    const int tid = threadIdx.x;
    const int wid = tid >> 5;
    const int lane = tid & 31;
    const int wr = wid >> 1;   // rows wr*32..+31
    const int wc = wid & 1;    // cols wc*64..+63

    const size_t eoff = (size_t)e * PH * PI;

    float acc[2][8][4];
#pragma unroll
    for (int mi = 0; mi < 2; mi++)
#pragma unroll
        for (int ni = 0; ni < 8; ni++)
#pragma unroll
            for (int q = 0; q < 4; q++) acc[mi][ni][q] = 0.0f;

    const uint32_t sb0 = smem_u32(smem);

    uint32_t offA[2][2], offB[4][2];
    {
        const int rA = wr * 32 + (lane & 15);
        const int cA = lane >> 4;
#pragma unroll
        for (int mi = 0; mi < 2; mi++)
#pragma unroll
            for (int ks = 0; ks < 2; ks++)
                offA[mi][ks] = SWO(rA + mi * 16, cA + 2 * ks);
        const int rB = (lane & 7) + 8 * ((lane >> 4) & 1);
        const int cB = (lane >> 3) & 1;
#pragma unroll
        for (int h = 0; h < 4; h++)
#pragma unroll
            for (int ks = 0; ks < 2; ks++)
                offB[h][ks] = SWO(wc * 64 + 16 * h + rB, cB + 2 * ks);
    }

    d_load_stage(sb0, row0, eoff, n0, 0, tid);
    CP_COMMIT();
    d_load_stage(sb0 + D_STAGE, row0, eoff, n0, 32, tid);
    CP_COMMIT();

    const int NC = PI / 32;  // 44
    int cb = 0, lb = 2;
    for (int c = 0; c < NC; c++) {
        CP_WAIT1();
        __syncthreads();
        if (c + 2 < NC)
            d_load_stage(sb0 + lb * D_STAGE, row0, eoff, n0, (c + 2) * 32, tid);
        CP_COMMIT();

        const uint32_t sb = sb0 + cb * D_STAGE;
#pragma unroll
        for (int ks = 0; ks < 2; ks++) {
            uint32_t ahi[2][4], alo[2][4];
            ldsm_x4(ahi[0], sb + offA[0][ks]);
            ldsm_x4(ahi[1], sb + offA[1][ks]);
            ldsm_x4(alo[0], sb + 8192 + offA[0][ks]);
            ldsm_x4(alo[1], sb + 8192 + offA[1][ks]);
#pragma unroll
            for (int h = 0; h < 4; h++) {
                uint32_t bh[4];
                ldsm_x4(bh, sb + 16384 + offB[h][ks]);
#pragma unroll
                for (int sub = 0; sub < 2; sub++) {
                    int ni = h * 2 + sub;
                    const uint32_t* ph = &bh[sub * 2];
#pragma unroll
                    for (int mi = 0; mi < 2; mi++) {
                        mma16816(acc[mi][ni], ahi[mi], ph);
                        mma16816(acc[mi][ni], alo[mi], ph);
                    }
                }
            }
        }
        cb = (cb == 2) ? 0 : cb + 1;
        lb = (lb == 2) ? 0 : lb + 1;
    }

    // epilogue: y[slot][col] = acc (plain stores; weights applied in combine)
    const int gRow = lane >> 2;
    const int cp2 = (lane & 3) * 2;
#pragma unroll
    for (int mi = 0; mi < 2; mi++) {
#pragma unroll
        for (int ni = 0; ni < 8; ni++) {
            int col = n0 + wc * 64 + ni * 8 + cp2;
            int r0 = wr * 32 + mi * 16 + gRow;
#pragma unroll
            for (int half_i = 0; half_i < 2; half_i++) {
                int lr = r0 + half_i * 8;
                int slot = row0 + lr;
                if (slot < end) {
                    float2 v;
                    v.x = acc[mi][ni][half_i * 2 + 0];
                    v.y = acc[mi][ni][half_i * 2 + 1];
                    *reinterpret_cast<float2*>(g_y + (size_t)slot * PH + col) = v;
                }
            }
        }
    }
}

// ---------------- combine: out[n] = w0*y[slot0] + w1*y[slot1] ----------------
__global__ void k_combine(const float* __restrict__ tw, float* __restrict__ out) {
    int idx = blockIdx.x * blockDim.x + threadIdx.x;  // over PN * (PH/4)
    if (idx >= PN * (PH / 4)) return;
    int n = idx / (PH / 4);
    int hq = idx % (PH / 4);
    int s0 = g_pair_slot[n * 2 + 0];
    int s1 = g_pair_slot[n * 2 + 1];
    float w0 = tw[n * 2 + 0];
    float w1 = tw[n * 2 + 1];
    float4 a = *reinterpret_cast<const float4*>(g_y + (size_t)s0 * PH + hq * 4);
    float4 b = *reinterpret_cast<const float4*>(g_y + (size_t)s1 * PH + hq * 4);
    float4 o;
    o.x = w0 * a.x + w1 * b.x;
    o.y = w0 * a.y + w1 * b.y;
    o.z = w0 * a.z + w1 * b.z;
    o.w = w0 * a.w + w1 * b.w;
    *reinterpret_cast<float4*>(out + (size_t)n * PH + hq * 4) = o;
}

// ---------------- launch ----------------
extern "C" void kernel_launch(void* const* d_in, const int* in_sizes, int n_in,
                              void* d_out, int out_size) {
    const float* x = (const float*)d_in[0];          // [N, H]
    const int* topk_ids = (const int*)d_in[1];       // [N, K]
    const float* topk_w = (const float*)d_in[2];     // [N, K]
    const float* Wg = (const float*)d_in[3];         // [E, I, H]
    const float* Wu = (const float*)d_in[4];         // [E, I, H]
    const float* Wd = (const float*)d_in[5];         // [E, H, I]
    float* out = (float*)d_out;                      // [N, H]

    static bool attr_done = false;
    if (!attr_done) {
        cudaFuncSetAttribute(k_gu, cudaFuncAttributeMaxDynamicSharedMemorySize, GU_SMEM);
        cudaFuncSetAttribute(k_down, cudaFuncAttributeMaxDynamicSharedMemorySize, D_SMEM);
        attr_done = true;
    }

    // launch index 0..2
    k_route<<<1, 256>>>(topk_ids);
    k_split_x<<<4096, 256>>>(x);
    k_split_wgu<<<8192, 256>>>(Wg, Wu);
    // launch index 3 == k_gu (ncu capture lands on the 4th launch)
    {
        dim3 grid(PN / 128, PI / 64, PE);    // 32 x 22 x 8
        k_gu<<<grid, 256, GU_SMEM>>>();
    }
    // launch index 4: wd rounding (needed only by k_down)
    k_split_wd<<<8192, 256>>>(Wd);
    // launch index 5
    {
        dim3 grid(PN / 128, PH / 128, PE);   // 32 x 16 x 8
        k_down<<<grid, 256, D_SMEM>>>();
    }
    // launch index 6
    k_combine<<<(PN * (PH / 4) + 255) / 256, 256>>>(topk_w, out);
}

// round 14
// speedup vs baseline: 6.4150x; 1.6045x over previous
#include <cuda_runtime.h>
#include <cuda_fp16.h>
#include <cstdint>

// Problem constants
#define PN 4096
#define PTOPK 2
#define PE 8
#define PH 2048
#define PI 1408
#define PNK (PN * PTOPK)   // 8192

// ---------------- device scratch ----------------
__device__ int g_offsets[PE + 1];
__device__ int g_pair_token[PNK];
__device__ int g_pair_slot[PNK];

__device__ __align__(16) __half g_xhi[(size_t)PN * PH];
__device__ __align__(16) __half g_wghi[(size_t)PE * PI * PH];
__device__ __align__(16) __half g_wuhi[(size_t)PE * PI * PH];
__device__ __align__(16) __half g_wdhi[(size_t)PE * PH * PI];
__device__ __align__(16) __half g_hhi[(size_t)PNK * PI];
__device__ __align__(16) float g_y[(size_t)PNK * PH];

// ---------------- helpers ----------------
__device__ __forceinline__ uint32_t smem_u32(const void* p) {
    return (uint32_t)__cvta_generic_to_shared(p);
}

__device__ __forceinline__ void cpa16(uint32_t dst, const void* src) {
    asm volatile("cp.async.cg.shared.global [%0], [%1], 16;" :: "r"(dst), "l"(src) : "memory");
}
#define CP_COMMIT() asm volatile("cp.async.commit_group;" ::: "memory")
#define CP_WAIT1()  asm volatile("cp.async.wait_group 1;" ::: "memory")

__device__ __forceinline__ void ldsm_x4(uint32_t* r, uint32_t addr) {
    asm volatile("ldmatrix.sync.aligned.m8n8.x4.shared.b16 {%0,%1,%2,%3}, [%4];"
                 : "=r"(r[0]), "=r"(r[1]), "=r"(r[2]), "=r"(r[3]) : "r"(addr) : "memory");
}
// fp16 mma, fp32 accumulate
__device__ __forceinline__ void mma16816(float* c, const uint32_t* a, const uint32_t* b) {
    asm volatile("mma.sync.aligned.m16n8k16.row.col.f32.f16.f16.f32 "
                 "{%0,%1,%2,%3}, {%4,%5,%6,%7}, {%8,%9}, {%0,%1,%2,%3};"
                 : "+f"(c[0]), "+f"(c[1]), "+f"(c[2]), "+f"(c[3])
                 : "r"(a[0]), "r"(a[1]), "r"(a[2]), "r"(a[3]), "r"(b[0]), "r"(b[1])
                 : "memory");
}

__device__ __forceinline__ float silu_f(float g) {
    return g / (1.0f + __expf(-g));
}

// 64B-pitch XOR swizzle: row r, 16B-chunk c (0..3). Conflict-free for
// cp.async stores and all ldmatrix phases.
#define SWO(r, c) ((uint32_t)((r) * 64 + ((((c) ^ (((r) >> 1) & 3))) * 16)))

// ---------------- routing: ONE single-CTA kernel ----------------
__global__ void k_route(const int* __restrict__ ids) {
    __shared__ int cnt[PE];
    __shared__ int off[PE + 1];
    __shared__ int cur[PE];
    const int tid = threadIdx.x;
    if (tid < PE) { cnt[tid] = 0; cur[tid] = 0; }
    __syncthreads();
    for (int i = tid; i < PNK; i += 256) atomicAdd(&cnt[ids[i]], 1);
    __syncthreads();
    if (tid == 0) {
        int s = 0;
        for (int e = 0; e < PE; e++) { off[e] = s; g_offsets[e] = s; s += cnt[e]; }
        off[PE] = s;
        g_offsets[PE] = s;
    }
    __syncthreads();
    for (int i = tid; i < PNK; i += 256) {
        int e = ids[i];
        int pos = off[e] + atomicAdd(&cur[e], 1);
        g_pair_token[pos] = i / PTOPK;
        g_pair_slot[i] = pos;
    }
}

// ---------------- fp32 -> fp16 rounding ----------------
// Destination globals referenced from DEVICE code only (host-shadow pitfall).
__device__ __forceinline__ void round_elem(const float* __restrict__ src,
                                           __half* __restrict__ hi, int i) {
    float4 v = reinterpret_cast<const float4*>(src)[i];
    __half2 h0, h1;
    h0.x = __float2half_rn(v.x);
    h0.y = __float2half_rn(v.y);
    h1.x = __float2half_rn(v.z);
    h1.y = __float2half_rn(v.w);
    reinterpret_cast<__half2*>(hi)[i * 2 + 0] = h0;
    reinterpret_cast<__half2*>(hi)[i * 2 + 1] = h1;
}

__global__ void k_split_x(const float* __restrict__ src) {
    const int n4 = PN * PH / 4;
    int i = blockIdx.x * blockDim.x + threadIdx.x;
    int stride = gridDim.x * blockDim.x;
    for (; i < n4; i += stride) round_elem(src, g_xhi, i);
}
__global__ void k_split_wgu(const float* __restrict__ wg, const float* __restrict__ wu) {
    const int n4 = PE * PI * PH / 4;
    int i = blockIdx.x * blockDim.x + threadIdx.x;
    int stride = gridDim.x * blockDim.x;
    for (; i < n4; i += stride) {
        round_elem(wg, g_wghi, i);
        round_elem(wu, g_wuhi, i);
    }
}
__global__ void k_split_wd(const float* __restrict__ src) {
    const int n4 = PE * PH * PI / 4;
    int i = blockIdx.x * blockDim.x + threadIdx.x;
    int stride = gridDim.x * blockDim.x;
    for (; i < n4; i += stride) round_elem(src, g_wdhi, i);
}

// ============================================================================
// GU kernel: single-term fp16 mma.sync, 128 slots x (64 gate + 64 up), BK=32.
// 3-stage cp.async pipeline, 64B-pitch XOR swizzle, one barrier per chunk.
// Stage (16384 B): A @0 (8K), Bg @8192 (4K), Bu @12288 (4K).
// ============================================================================
#define GU_STAGE 16384
#define GU_SMEM  (3 * GU_STAGE + 512)

__device__ __forceinline__ void gu_load_stage(uint32_t sb, const int* s_tok, size_t eoff,
                                              int n0, int k0, int tid) {
#pragma unroll
    for (int it = 0; it < 2; it++) {
        int idx = tid + it * 256;          // 0..511 : A
        int r = idx >> 2;                  // 0..127
        int c = idx & 3;
        const __half* src = g_xhi + (size_t)s_tok[r] * PH + k0 + c * 8;
        cpa16(sb + SWO(r, c), src);
    }
#pragma unroll
    for (int it = 0; it < 2; it++) {
        int idx = tid + it * 256;          // 0..511 : Bg, Bu
        int t = idx >> 8;                  // 0..1
        int r = (idx >> 2) & 63;
        int c = idx & 3;
        const __half* base = t ? g_wuhi : g_wghi;
        const __half* src = base + eoff + (size_t)(n0 + r) * PH + k0 + c * 8;
        cpa16(sb + 8192 + t * 4096 + SWO(r, c), src);
    }
}

__global__ __launch_bounds__(256, 2) void k_gu() {
    extern __shared__ __align__(128) char smem[];
    const int e = blockIdx.z;
    const int beg = g_offsets[e];
    const int end = g_offsets[e + 1];
    const int row0 = beg + blockIdx.x * 128;
    if (row0 >= end) return;
    const int n0 = blockIdx.y * 64;

    const int tid = threadIdx.x;
    const int wid = tid >> 5;
    const int lane = tid & 31;
    const int wr = wid >> 1;   // rows wr*32..+31
    const int wc = wid & 1;    // cols wc*32..+31

    int* s_tok = reinterpret_cast<int*>(smem + 3 * GU_STAGE);
    if (tid < 128) {
        int slot = row0 + tid;
        if (slot >= PNK) slot = PNK - 1;
        s_tok[tid] = g_pair_token[slot];
    }
    __syncthreads();

    const size_t eoff = (size_t)e * PI * PH;

    float accg[2][4][4];
    float accu[2][4][4];
#pragma unroll
    for (int mi = 0; mi < 2; mi++)
#pragma unroll
        for (int ni = 0; ni < 4; ni++)
#pragma unroll
            for (int q = 0; q < 4; q++) { accg[mi][ni][q] = 0.0f; accu[mi][ni][q] = 0.0f; }

    const uint32_t sb0 = smem_u32(smem);

    uint32_t offA[2][2], offB[2][2];
    {
        const int rA = wr * 32 + (lane & 15);
        const int cA = lane >> 4;
#pragma unroll
        for (int mi = 0; mi < 2; mi++)
#pragma unroll
            for (int ks = 0; ks < 2; ks++)
                offA[mi][ks] = SWO(rA + mi * 16, cA + 2 * ks);
        const int rB = (lane & 7) + 8 * ((lane >> 4) & 1);
        const int cB = (lane >> 3) & 1;
#pragma unroll
        for (int h = 0; h < 2; h++)
#pragma unroll
            for (int ks = 0; ks < 2; ks++)
                offB[h][ks] = SWO(wc * 32 + 16 * h + rB, cB + 2 * ks);
    }

    gu_load_stage(sb0, s_tok, eoff, n0, 0, tid);
    CP_COMMIT();
    gu_load_stage(sb0 + GU_STAGE, s_tok, eoff, n0, 32, tid);
    CP_COMMIT();

    const int NC = PH / 32;  // 64
    int cb = 0, lb = 2;
    for (int c = 0; c < NC; c++) {
        CP_WAIT1();
        __syncthreads();
        if (c + 2 < NC)
            gu_load_stage(sb0 + lb * GU_STAGE, s_tok, eoff, n0, (c + 2) * 32, tid);
        CP_COMMIT();

        const uint32_t sb = sb0 + cb * GU_STAGE;
#pragma unroll
        for (int ks = 0; ks < 2; ks++) {
            uint32_t ahi[2][4];
            ldsm_x4(ahi[0], sb + offA[0][ks]);
            ldsm_x4(ahi[1], sb + offA[1][ks]);
            {   // gate
                uint32_t bh[8];
                ldsm_x4(bh + 0, sb + 8192 + offB[0][ks]);
                ldsm_x4(bh + 4, sb + 8192 + offB[1][ks]);
#pragma unroll
                for (int ni = 0; ni < 4; ni++) {
                    const uint32_t* ph = &bh[(ni >> 1) * 4 + (ni & 1) * 2];
#pragma unroll
                    for (int mi = 0; mi < 2; mi++)
                        mma16816(accg[mi][ni], ahi[mi], ph);
                }
            }
            {   // up
                uint32_t bh[8];
                ldsm_x4(bh + 0, sb + 12288 + offB[0][ks]);
                ldsm_x4(bh + 4, sb + 12288 + offB[1][ks]);
#pragma unroll
                for (int ni = 0; ni < 4; ni++) {
                    const uint32_t* ph = &bh[(ni >> 1) * 4 + (ni & 1) * 2];
#pragma unroll
                    for (int mi = 0; mi < 2; mi++)
                        mma16816(accu[mi][ni], ahi[mi], ph);
                }
            }
        }
        cb = (cb == 2) ? 0 : cb + 1;
        lb = (lb == 2) ? 0 : lb + 1;
    }

    // epilogue: h = silu(g)*u -> fp16
    const int gRow = lane >> 2;
    const int cp2 = (lane & 3) * 2;
#pragma unroll
    for (int mi = 0; mi < 2; mi++) {
#pragma unroll
        for (int ni = 0; ni < 4; ni++) {
            int col = n0 + wc * 32 + ni * 8 + cp2;
            int r0 = wr * 32 + mi * 16 + gRow;
#pragma unroll
            for (int half_i = 0; half_i < 2; half_i++) {
                int slot = row0 + r0 + half_i * 8;
                if (slot < end) {
                    float g0 = accg[mi][ni][half_i * 2 + 0];
                    float g1 = accg[mi][ni][half_i * 2 + 1];
                    float u0 = accu[mi][ni][half_i * 2 + 0];
                    float u1 = accu[mi][ni][half_i * 2 + 1];
                    __half2 vh;
                    vh.x = __float2half_rn(silu_f(g0) * u0);
                    vh.y = __float2half_rn(silu_f(g1) * u1);
                    *reinterpret_cast<__half2*>(g_hhi + (size_t)slot * PI + col) = vh;
                }
            }
        }
    }
}

// ============================================================================
// Down kernel: single-term fp16, 128 slots x 128 H-cols, BK=32 over I.
// Stage (16384 B): A @0 (8K), B @8192 (8K).
// ============================================================================
#define D_STAGE 16384
#define D_SMEM  (3 * D_STAGE + 512)

__device__ __forceinline__ void d_load_stage(uint32_t sb, int row0, size_t eoff,
                                             int n0, int k0, int tid) {
#pragma unroll
    for (int it = 0; it < 2; it++) {
        int idx = tid + it * 256;          // A
        int r = idx >> 2;
        int c = idx & 3;
        int slot = row0 + r;
        if (slot >= PNK) slot = PNK - 1;
        const __half* src = g_hhi + (size_t)slot * PI + k0 + c * 8;
        cpa16(sb + SWO(r, c), src);
    }
#pragma unroll
    for (int it = 0; it < 2; it++) {
        int idx = tid + it * 256;          // B (wd), 128 rows
        int r = idx >> 2;
        int c = idx & 3;
        const __half* src = g_wdhi + eoff + (size_t)(n0 + r) * PI + k0 + c * 8;
        cpa16(sb + 8192 + SWO(r, c), src);
    }
}

__global__ __launch_bounds__(256, 2) void k_down() {
    extern __shared__ __align__(128) char smem[];
    const int e = blockIdx.z;
    const int beg = g_offsets[e];
    const int end = g_offsets[e + 1];
    const int row0 = beg + blockIdx.x * 128;
    if (row0 >= end) return;
    const int n0 = blockIdx.y * 128;

    const int tid = threadIdx.x;
    const int wid = tid >> 5;
    const int lane = tid & 31;
    const int wr = wid >> 1;   // rows wr*32..+31
    const int wc = wid & 1;    // cols wc*64..+63

    const size_t eoff = (size_t)e * PH * PI;

    float acc[2][8][4];
#pragma unroll
    for (int mi = 0; mi < 2; mi++)
#pragma unroll
        for (int ni = 0; ni < 8; ni++)
#pragma unroll
            for (int q = 0; q < 4; q++) acc[mi][ni][q] = 0.0f;

    const uint32_t sb0 = smem_u32(smem);

    uint32_t offA[2][2], offB[4][2];
    {
        const int rA = wr * 32 + (lane & 15);
        const int cA = lane >> 4;
#pragma unroll
        for (int mi = 0; mi < 2; mi++)
#pragma unroll
            for (int ks = 0; ks < 2; ks++)
                offA[mi][ks] = SWO(rA + mi * 16, cA + 2 * ks);
        const int rB = (lane & 7) + 8 * ((lane >> 4) & 1);
        const int cB = (lane >> 3) & 1;
#pragma unroll
        for (int h = 0; h < 4; h++)
#pragma unroll
            for (int ks = 0; ks < 2; ks++)
                offB[h][ks] = SWO(wc * 64 + 16 * h + rB, cB + 2 * ks);
    }

    d_load_stage(sb0, row0, eoff, n0, 0, tid);
    CP_COMMIT();
    d_load_stage(sb0 + D_STAGE, row0, eoff, n0, 32, tid);
    CP_COMMIT();

    const int NC = PI / 32;  // 44
    int cb = 0, lb = 2;
    for (int c = 0; c < NC; c++) {
        CP_WAIT1();
        __syncthreads();
        if (c + 2 < NC)
            d_load_stage(sb0 + lb * D_STAGE, row0, eoff, n0, (c + 2) * 32, tid);
        CP_COMMIT();

        const uint32_t sb = sb0 + cb * D_STAGE;
#pragma unroll
        for (int ks = 0; ks < 2; ks++) {
            uint32_t ahi[2][4];
            ldsm_x4(ahi[0], sb + offA[0][ks]);
            ldsm_x4(ahi[1], sb + offA[1][ks]);
#pragma unroll
            for (int h = 0; h < 4; h++) {
                uint32_t bh[4];
                ldsm_x4(bh, sb + 8192 + offB[h][ks]);
#pragma unroll
                for (int sub = 0; sub < 2; sub++) {
                    int ni = h * 2 + sub;
                    const uint32_t* ph = &bh[sub * 2];
#pragma unroll
                    for (int mi = 0; mi < 2; mi++)
                        mma16816(acc[mi][ni], ahi[mi], ph);
                }
            }
        }
        cb = (cb == 2) ? 0 : cb + 1;
        lb = (lb == 2) ? 0 : lb + 1;
    }

    // epilogue: y[slot][col] = acc (plain stores; weights applied in combine)
    const int gRow = lane >> 2;
    const int cp2 = (lane & 3) * 2;
#pragma unroll
    for (int mi = 0; mi < 2; mi++) {
#pragma unroll
        for (int ni = 0; ni < 8; ni++) {
            int col = n0 + wc * 64 + ni * 8 + cp2;
            int r0 = wr * 32 + mi * 16 + gRow;
#pragma unroll
            for (int half_i = 0; half_i < 2; half_i++) {
                int lr = r0 + half_i * 8;
                int slot = row0 + lr;
                if (slot < end) {
                    float2 v;
                    v.x = acc[mi][ni][half_i * 2 + 0];
                    v.y = acc[mi][ni][half_i * 2 + 1];
                    *reinterpret_cast<float2*>(g_y + (size_t)slot * PH + col) = v;
                }
            }
        }
    }
}

// ---------------- combine: out[n] = w0*y[slot0] + w1*y[slot1] ----------------
__global__ void k_combine(const float* __restrict__ tw, float* __restrict__ out) {
    int idx = blockIdx.x * blockDim.x + threadIdx.x;  // over PN * (PH/4)
    if (idx >= PN * (PH / 4)) return;
    int n = idx / (PH / 4);
    int hq = idx % (PH / 4);
    int s0 = g_pair_slot[n * 2 + 0];
    int s1 = g_pair_slot[n * 2 + 1];
    float w0 = tw[n * 2 + 0];
    float w1 = tw[n * 2 + 1];
    float4 a = *reinterpret_cast<const float4*>(g_y + (size_t)s0 * PH + hq * 4);
    float4 b = *reinterpret_cast<const float4*>(g_y + (size_t)s1 * PH + hq * 4);
    float4 o;
    o.x = w0 * a.x + w1 * b.x;
    o.y = w0 * a.y + w1 * b.y;
    o.z = w0 * a.z + w1 * b.z;
    o.w = w0 * a.w + w1 * b.w;
    *reinterpret_cast<float4*>(out + (size_t)n * PH + hq * 4) = o;
}

// ---------------- launch ----------------
extern "C" void kernel_launch(void* const* d_in, const int* in_sizes, int n_in,
                              void* d_out, int out_size) {
    const float* x = (const float*)d_in[0];          // [N, H]
    const int* topk_ids = (const int*)d_in[1];       // [N, K]
    const float* topk_w = (const float*)d_in[2];     // [N, K]
    const float* Wg = (const float*)d_in[3];         // [E, I, H]
    const float* Wu = (const float*)d_in[4];         // [E, I, H]
    const float* Wd = (const float*)d_in[5];         // [E, H, I]
    float* out = (float*)d_out;                      // [N, H]

    static bool attr_done = false;
    if (!attr_done) {
        cudaFuncSetAttribute(k_gu, cudaFuncAttributeMaxDynamicSharedMemorySize, GU_SMEM);
        cudaFuncSetAttribute(k_down, cudaFuncAttributeMaxDynamicSharedMemorySize, D_SMEM);
        attr_done = true;
    }

    // launch index 0..2
    k_route<<<1, 256>>>(topk_ids);
    k_split_x<<<4096, 256>>>(x);
    k_split_wgu<<<8192, 256>>>(Wg, Wu);
    // launch index 3 == k_gu (ncu capture lands on the 4th launch)
    {
        dim3 grid(PN / 128, PI / 64, PE);    // 32 x 22 x 8
        k_gu<<<grid, 256, GU_SMEM>>>();
    }
    // launch index 4: wd rounding (needed only by k_down)
    k_split_wd<<<8192, 256>>>(Wd);
    // launch index 5
    {
        dim3 grid(PN / 128, PH / 128, PE);   // 32 x 16 x 8
        k_down<<<grid, 256, D_SMEM>>>();
    }
    // launch index 6
    k_combine<<<(PN * (PH / 4) + 255) / 256, 256>>>(topk_w, out);
}

// round 15
// speedup vs baseline: 6.9422x; 1.0822x over previous
#include <cuda_runtime.h>
#include <cuda_fp16.h>
#include <cstdint>

// Problem constants
#define PN 4096
#define PTOPK 2
#define PE 8
#define PH 2048
#define PI 1408
#define PNK (PN * PTOPK)   // 8192

// ---------------- device scratch ----------------
__device__ int g_offsets[PE + 1];
__device__ int g_pair_token[PNK];
__device__ int g_pair_slot[PNK];

__device__ __align__(16) __half g_xhi[(size_t)PN * PH];
__device__ __align__(16) __half g_wghi[(size_t)PE * PI * PH];
__device__ __align__(16) __half g_wuhi[(size_t)PE * PI * PH];
__device__ __align__(16) __half g_wdhi[(size_t)PE * PH * PI];
__device__ __align__(16) __half g_hhi[(size_t)PNK * PI];
__device__ __align__(16) float g_y[(size_t)PNK * PH];

// ---------------- helpers ----------------
__device__ __forceinline__ uint32_t smem_u32(const void* p) {
    return (uint32_t)__cvta_generic_to_shared(p);
}

__device__ __forceinline__ void cpa16(uint32_t dst, const void* src) {
    asm volatile("cp.async.cg.shared.global [%0], [%1], 16;" :: "r"(dst), "l"(src) : "memory");
}
#define CP_COMMIT() asm volatile("cp.async.commit_group;" ::: "memory")
#define CP_WAIT1()  asm volatile("cp.async.wait_group 1;" ::: "memory")

__device__ __forceinline__ void ldsm_x4(uint32_t* r, uint32_t addr) {
    asm volatile("ldmatrix.sync.aligned.m8n8.x4.shared.b16 {%0,%1,%2,%3}, [%4];"
                 : "=r"(r[0]), "=r"(r[1]), "=r"(r[2]), "=r"(r[3]) : "r"(addr) : "memory");
}
// fp16 mma, fp32 accumulate
__device__ __forceinline__ void mma16816(float* c, const uint32_t* a, const uint32_t* b) {
    asm volatile("mma.sync.aligned.m16n8k16.row.col.f32.f16.f16.f32 "
                 "{%0,%1,%2,%3}, {%4,%5,%6,%7}, {%8,%9}, {%0,%1,%2,%3};"
                 : "+f"(c[0]), "+f"(c[1]), "+f"(c[2]), "+f"(c[3])
                 : "r"(a[0]), "r"(a[1]), "r"(a[2]), "r"(a[3]), "r"(b[0]), "r"(b[1])
                 : "memory");
}

__device__ __forceinline__ float silu_f(float g) {
    return g / (1.0f + __expf(-g));
}

// SW128 swizzle: row r (128B pitch), 16B-chunk c (0..7): chunk' = c ^ (r & 7).
// Conflict-free for cp.async stores (bijective per row) and ldmatrix phases
// (8 rows of a phase hit 8 distinct chunks).
#define SWZ128(r, c) ((uint32_t)((r) * 128 + ((((c) ^ ((r) & 7))) << 4)))

// ---------------- routing: ONE single-CTA kernel ----------------
__global__ void k_route(const int* __restrict__ ids) {
    __shared__ int cnt[PE];
    __shared__ int off[PE + 1];
    __shared__ int cur[PE];
    const int tid = threadIdx.x;
    if (tid < PE) { cnt[tid] = 0; cur[tid] = 0; }
    __syncthreads();
    for (int i = tid; i < PNK; i += 256) atomicAdd(&cnt[ids[i]], 1);
    __syncthreads();
    if (tid == 0) {
        int s = 0;
        for (int e = 0; e < PE; e++) { off[e] = s; g_offsets[e] = s; s += cnt[e]; }
        off[PE] = s;
        g_offsets[PE] = s;
    }
    __syncthreads();
    for (int i = tid; i < PNK; i += 256) {
        int e = ids[i];
        int pos = off[e] + atomicAdd(&cur[e], 1);
        g_pair_token[pos] = i / PTOPK;
        g_pair_slot[i] = pos;
    }
}

// ---------------- fp32 -> fp16 rounding ----------------
// Destination globals referenced from DEVICE code only (host-shadow pitfall).
__device__ __forceinline__ void round_elem(const float* __restrict__ src,
                                           __half* __restrict__ hi, int i) {
    float4 v = reinterpret_cast<const float4*>(src)[i];
    __half2 h0, h1;
    h0.x = __float2half_rn(v.x);
    h0.y = __float2half_rn(v.y);
    h1.x = __float2half_rn(v.z);
    h1.y = __float2half_rn(v.w);
    reinterpret_cast<__half2*>(hi)[i * 2 + 0] = h0;
    reinterpret_cast<__half2*>(hi)[i * 2 + 1] = h1;
}

__global__ void k_split_x(const float* __restrict__ src) {
    const int n4 = PN * PH / 4;
    int i = blockIdx.x * blockDim.x + threadIdx.x;
    int stride = gridDim.x * blockDim.x;
    for (; i < n4; i += stride) round_elem(src, g_xhi, i);
}
__global__ void k_split_wgu(const float* __restrict__ wg, const float* __restrict__ wu) {
    const int n4 = PE * PI * PH / 4;
    int i = blockIdx.x * blockDim.x + threadIdx.x;
    int stride = gridDim.x * blockDim.x;
    for (; i < n4; i += stride) {
        round_elem(wg, g_wghi, i);
        round_elem(wu, g_wuhi, i);
    }
}
__global__ void k_split_wd(const float* __restrict__ src) {
    const int n4 = PE * PH * PI / 4;
    int i = blockIdx.x * blockDim.x + threadIdx.x;
    int stride = gridDim.x * blockDim.x;
    for (; i < n4; i += stride) round_elem(src, g_wdhi, i);
}

// ============================================================================
// GU kernel: single-term fp16 mma.sync, 128 slots x (64 gate + 64 up), BK=64.
// 3-stage cp.async pipeline, SW128 swizzle (128B rows), one barrier per chunk.
// Stage (32768 B): A @0 (16K), Bg @16384 (8K), Bu @24576 (8K).
// ============================================================================
#define GU_STAGE 32768
#define GU_SMEM  (3 * GU_STAGE + 512)

__device__ __forceinline__ void gu_load_stage(uint32_t sb, const int* s_tok, size_t eoff,
                                              int n0, int k0, int tid) {
#pragma unroll
    for (int it = 0; it < 4; it++) {
        int idx = tid + it * 256;          // 0..1023 : A (128 rows x 8 chunks)
        int r = idx >> 3;
        int c = idx & 7;
        const __half* src = g_xhi + (size_t)s_tok[r] * PH + k0 + c * 8;
        cpa16(sb + SWZ128(r, c), src);
    }
#pragma unroll
    for (int it = 0; it < 4; it++) {
        int idx = tid + it * 256;          // 0..1023 : Bg, Bu (2 x 64 rows x 8)
        int t = idx >> 9;                  // 0..1
        int r = (idx >> 3) & 63;
        int c = idx & 7;
        const __half* base = t ? g_wuhi : g_wghi;
        const __half* src = base + eoff + (size_t)(n0 + r) * PH + k0 + c * 8;
        cpa16(sb + 16384 + t * 8192 + SWZ128(r, c), src);
    }
}

__global__ __launch_bounds__(256, 2) void k_gu() {
    extern __shared__ __align__(128) char smem[];
    const int e = blockIdx.z;
    const int beg = g_offsets[e];
    const int end = g_offsets[e + 1];
    const int row0 = beg + blockIdx.x * 128;
    if (row0 >= end) return;
    const int n0 = blockIdx.y * 64;

    const int tid = threadIdx.x;
    const int wid = tid >> 5;
    const int lane = tid & 31;
    const int wr = wid >> 1;   // rows wr*32..+31
    const int wc = wid & 1;    // cols wc*32..+31

    int* s_tok = reinterpret_cast<int*>(smem + 3 * GU_STAGE);
    if (tid < 128) {
        int slot = row0 + tid;
        if (slot >= PNK) slot = PNK - 1;
        s_tok[tid] = g_pair_token[slot];
    }
    __syncthreads();

    const size_t eoff = (size_t)e * PI * PH;

    float accg[2][4][4];
    float accu[2][4][4];
#pragma unroll
    for (int mi = 0; mi < 2; mi++)
#pragma unroll
        for (int ni = 0; ni < 4; ni++)
#pragma unroll
            for (int q = 0; q < 4; q++) { accg[mi][ni][q] = 0.0f; accu[mi][ni][q] = 0.0f; }

    const uint32_t sb0 = smem_u32(smem);

    // on-the-fly ldsm address bases (SW128: xor term depends on (lane&7))
    const int rA = wr * 32 + (lane & 15);
    const uint32_t aRow0 = (uint32_t)rA * 128;           // stage-relative; +2048 for mi=1
    const int aC = lane >> 4;                            // base chunk for A
    const int x7 = lane & 7;
    const int rBl = (lane & 7) + 8 * ((lane >> 4) & 1);
    const uint32_t bRow0 = (uint32_t)(wc * 32 + rBl) * 128;  // +2048 for h=1
    const int bC = (lane >> 3) & 1;

    gu_load_stage(sb0, s_tok, eoff, n0, 0, tid);
    CP_COMMIT();
    gu_load_stage(sb0 + GU_STAGE, s_tok, eoff, n0, 64, tid);
    CP_COMMIT();

    const int NC = PH / 64;  // 32
    int cb = 0, lb = 2;
    for (int c = 0; c < NC; c++) {
        CP_WAIT1();
        __syncthreads();
        if (c + 2 < NC)
            gu_load_stage(sb0 + lb * GU_STAGE, s_tok, eoff, n0, (c + 2) * 64, tid);
        CP_COMMIT();

        const uint32_t sbA = sb0 + cb * GU_STAGE;
        const uint32_t sbBg = sbA + 16384;
        const uint32_t sbBu = sbA + 24576;
#pragma unroll
        for (int ks = 0; ks < 4; ks++) {
            const uint32_t tA = (uint32_t)(((aC + 2 * ks) ^ x7) << 4);
            const uint32_t tB = (uint32_t)(((bC + 2 * ks) ^ x7) << 4);
            uint32_t ahi[2][4];
            ldsm_x4(ahi[0], sbA + aRow0 + tA);
            ldsm_x4(ahi[1], sbA + aRow0 + 2048 + tA);
            {   // gate
                uint32_t bh[8];
                ldsm_x4(bh + 0, sbBg + bRow0 + tB);
                ldsm_x4(bh + 4, sbBg + bRow0 + 2048 + tB);
#pragma unroll
                for (int ni = 0; ni < 4; ni++) {
                    const uint32_t* ph = &bh[(ni >> 1) * 4 + (ni & 1) * 2];
#pragma unroll
                    for (int mi = 0; mi < 2; mi++)
                        mma16816(accg[mi][ni], ahi[mi], ph);
                }
            }
            {   // up
                uint32_t bh[8];
                ldsm_x4(bh + 0, sbBu + bRow0 + tB);
                ldsm_x4(bh + 4, sbBu + bRow0 + 2048 + tB);
#pragma unroll
                for (int ni = 0; ni < 4; ni++) {
                    const uint32_t* ph = &bh[(ni >> 1) * 4 + (ni & 1) * 2];
#pragma unroll
                    for (int mi = 0; mi < 2; mi++)
                        mma16816(accu[mi][ni], ahi[mi], ph);
                }
            }
        }
        cb = (cb == 2) ? 0 : cb + 1;
        lb = (lb == 2) ? 0 : lb + 1;
    }

    // epilogue: h = silu(g)*u -> fp16
    const int gRow = lane >> 2;
    const int cp2 = (lane & 3) * 2;
#pragma unroll
    for (int mi = 0; mi < 2; mi++) {
#pragma unroll
        for (int ni = 0; ni < 4; ni++) {
            int col = n0 + wc * 32 + ni * 8 + cp2;
            int r0 = wr * 32 + mi * 16 + gRow;
#pragma unroll
            for (int half_i = 0; half_i < 2; half_i++) {
                int slot = row0 + r0 + half_i * 8;
                if (slot < end) {
                    float g0 = accg[mi][ni][half_i * 2 + 0];
                    float g1 = accg[mi][ni][half_i * 2 + 1];
                    float u0 = accu[mi][ni][half_i * 2 + 0];
                    float u1 = accu[mi][ni][half_i * 2 + 1];
                    __half2 vh;
                    vh.x = __float2half_rn(silu_f(g0) * u0);
                    vh.y = __float2half_rn(silu_f(g1) * u1);
                    *reinterpret_cast<__half2*>(g_hhi + (size_t)slot * PI + col) = vh;
                }
            }
        }
    }
}

// ============================================================================
// Down kernel: single-term fp16, 128 slots x 128 H-cols, BK=64 over I.
// Stage (32768 B): A @0 (16K), B @16384 (16K).
// ============================================================================
#define D_STAGE 32768
#define D_SMEM  (3 * D_STAGE + 512)

__device__ __forceinline__ void d_load_stage(uint32_t sb, int row0, size_t eoff,
                                             int n0, int k0, int tid) {
#pragma unroll
    for (int it = 0; it < 4; it++) {
        int idx = tid + it * 256;          // A (128 rows x 8 chunks)
        int r = idx >> 3;
        int c = idx & 7;
        int slot = row0 + r;
        if (slot >= PNK) slot = PNK - 1;
        const __half* src = g_hhi + (size_t)slot * PI + k0 + c * 8;
        cpa16(sb + SWZ128(r, c), src);
    }
#pragma unroll
    for (int it = 0; it < 4; it++) {
        int idx = tid + it * 256;          // B (128 rows x 8 chunks)
        int r = idx >> 3;
        int c = idx & 7;
        const __half* src = g_wdhi + eoff + (size_t)(n0 + r) * PI + k0 + c * 8;
        cpa16(sb + 16384 + SWZ128(r, c), src);
    }
}

__global__ __launch_bounds__(256, 2) void k_down() {
    extern __shared__ __align__(128) char smem[];
    const int e = blockIdx.z;
    const int beg = g_offsets[e];
    const int end = g_offsets[e + 1];
    const int row0 = beg + blockIdx.x * 128;
    if (row0 >= end) return;
    const int n0 = blockIdx.y * 128;

    const int tid = threadIdx.x;
    const int wid = tid >> 5;
    const int lane = tid & 31;
    const int wr = wid >> 1;   // rows wr*32..+31
    const int wc = wid & 1;    // cols wc*64..+63

    const size_t eoff = (size_t)e * PH * PI;

    float acc[2][8][4];
#pragma unroll
    for (int mi = 0; mi < 2; mi++)
#pragma unroll
        for (int ni = 0; ni < 8; ni++)
#pragma unroll
            for (int q = 0; q < 4; q++) acc[mi][ni][q] = 0.0f;

    const uint32_t sb0 = smem_u32(smem);

    const int rA = wr * 32 + (lane & 15);
    const uint32_t aRow0 = (uint32_t)rA * 128;
    const int aC = lane >> 4;
    const int x7 = lane & 7;
    const int rBl = (lane & 7) + 8 * ((lane >> 4) & 1);
    const uint32_t bRow0 = (uint32_t)(wc * 64 + rBl) * 128;  // + h*2048
    const int bC = (lane >> 3) & 1;

    d_load_stage(sb0, row0, eoff, n0, 0, tid);
    CP_COMMIT();
    d_load_stage(sb0 + D_STAGE, row0, eoff, n0, 64, tid);
    CP_COMMIT();

    const int NC = PI / 64;  // 22
    int cb = 0, lb = 2;
    for (int c = 0; c < NC; c++) {
        CP_WAIT1();
        __syncthreads();
        if (c + 2 < NC)
            d_load_stage(sb0 + lb * D_STAGE, row0, eoff, n0, (c + 2) * 64, tid);
        CP_COMMIT();

        const uint32_t sbA = sb0 + cb * D_STAGE;
        const uint32_t sbB = sbA + 16384;
#pragma unroll
        for (int ks = 0; ks < 4; ks++) {
            const uint32_t tA = (uint32_t)(((aC + 2 * ks) ^ x7) << 4);
            const uint32_t tB = (uint32_t)(((bC + 2 * ks) ^ x7) << 4);
            uint32_t ahi[2][4];
            ldsm_x4(ahi[0], sbA + aRow0 + tA);
            ldsm_x4(ahi[1], sbA + aRow0 + 2048 + tA);
#pragma unroll
            for (int h = 0; h < 4; h++) {
                uint32_t bh[4];
                ldsm_x4(bh, sbB + bRow0 + h * 2048 + tB);
#pragma unroll
                for (int sub = 0; sub < 2; sub++) {
                    int ni = h * 2 + sub;
                    const uint32_t* ph = &bh[sub * 2];
#pragma unroll
                    for (int mi = 0; mi < 2; mi++)
                        mma16816(acc[mi][ni], ahi[mi], ph);
                }
            }
        }
        cb = (cb == 2) ? 0 : cb + 1;
        lb = (lb == 2) ? 0 : lb + 1;
    }

    // epilogue: y[slot][col] = acc (plain stores; weights applied in combine)
    const int gRow = lane >> 2;
    const int cp2 = (lane & 3) * 2;
#pragma unroll
    for (int mi = 0; mi < 2; mi++) {
#pragma unroll
        for (int ni = 0; ni < 8; ni++) {
            int col = n0 + wc * 64 + ni * 8 + cp2;
            int r0 = wr * 32 + mi * 16 + gRow;
#pragma unroll
            for (int half_i = 0; half_i < 2; half_i++) {
                int lr = r0 + half_i * 8;
                int slot = row0 + lr;
                if (slot < end) {
                    float2 v;
                    v.x = acc[mi][ni][half_i * 2 + 0];
                    v.y = acc[mi][ni][half_i * 2 + 1];
                    *reinterpret_cast<float2*>(g_y + (size_t)slot * PH + col) = v;
                }
            }
        }
    }
}

// ---------------- combine: out[n] = w0*y[slot0] + w1*y[slot1] ----------------
__global__ void k_combine(const float* __restrict__ tw, float* __restrict__ out) {
    int idx = blockIdx.x * blockDim.x + threadIdx.x;  // over PN * (PH/4)
    if (idx >= PN * (PH / 4)) return;
    int n = idx / (PH / 4);
    int hq = idx % (PH / 4);
    int s0 = g_pair_slot[n * 2 + 0];
    int s1 = g_pair_slot[n * 2 + 1];
    float w0 = tw[n * 2 + 0];
    float w1 = tw[n * 2 + 1];
    float4 a = *reinterpret_cast<const float4*>(g_y + (size_t)s0 * PH + hq * 4);
    float4 b = *reinterpret_cast<const float4*>(g_y + (size_t)s1 * PH + hq * 4);
    float4 o;
    o.x = w0 * a.x + w1 * b.x;
    o.y = w0 * a.y + w1 * b.y;
    o.z = w0 * a.z + w1 * b.z;
    o.w = w0 * a.w + w1 * b.w;
    *reinterpret_cast<float4*>(out + (size_t)n * PH + hq * 4) = o;
}

// ---------------- launch ----------------
extern "C" void kernel_launch(void* const* d_in, const int* in_sizes, int n_in,
                              void* d_out, int out_size) {
    const float* x = (const float*)d_in[0];          // [N, H]
    const int* topk_ids = (const int*)d_in[1];       // [N, K]
    const float* topk_w = (const float*)d_in[2];     // [N, K]
    const float* Wg = (const float*)d_in[3];         // [E, I, H]
    const float* Wu = (const float*)d_in[4];         // [E, I, H]
    const float* Wd = (const float*)d_in[5];         // [E, H, I]
    float* out = (float*)d_out;                      // [N, H]

    static bool attr_done = false;
    if (!attr_done) {
        cudaFuncSetAttribute(k_gu, cudaFuncAttributeMaxDynamicSharedMemorySize, GU_SMEM);
        cudaFuncSetAttribute(k_down, cudaFuncAttributeMaxDynamicSharedMemorySize, D_SMEM);
        attr_done = true;
    }

    // launch index 0..2
    k_route<<<1, 256>>>(topk_ids);
    k_split_x<<<4096, 256>>>(x);
    k_split_wgu<<<8192, 256>>>(Wg, Wu);
    // launch index 3 == k_gu (ncu capture lands on the 4th launch)
    {
        dim3 grid(PN / 128, PI / 64, PE);    // 32 x 22 x 8
        k_gu<<<grid, 256, GU_SMEM>>>();
    }
    // launch index 4: wd rounding (needed only by k_down)
    k_split_wd<<<8192, 256>>>(Wd);
    // launch index 5
    {
        dim3 grid(PN / 128, PH / 128, PE);   // 32 x 16 x 8
        k_down<<<grid, 256, D_SMEM>>>();
    }
    // launch index 6
    k_combine<<<(PN * (PH / 4) + 255) / 256, 256>>>(topk_w, out);
}